// round 1
// baseline (speedup 1.0000x reference)
#include <cuda_runtime.h>
#include <math.h>
#include <stdint.h>

// ---------------------------------------------------------------------------
// Problem constants
// ---------------------------------------------------------------------------
// node types: [author, field_of_study, institution, paper]
// NUMS = [200000, 30000, 5000, 150000], total 385000
// 7 relations, E = 400000 edges each
// layer1: 128 -> 256 (H=8 heads, NB=4 bases, DH=32)
// layer2: 256 -> 349
// ---------------------------------------------------------------------------

enum { F_RELU = 1, F_SCALE = 2, F_BIAS = 4, F_ACCUM = 8, F_BKN = 16 };

// Persistent scratch (no allocations allowed). ~955 MB total.
__device__ float g_bases[(size_t)385000 * 128];   // base projections, all types
__device__ float g_out1 [(size_t)385000 * 256];   // layer-1 pre-relu hidden
__device__ float g_w    [(size_t)200000 * 64];    // per-node rel/root weights (reused)
__device__ float g_sum  [(size_t)200000 * 256];   // segment sums (reused, 128 or 256 wide)
__device__ float g_max  [(size_t)200000 * 128];   // segment max (layer 1)
__device__ int   g_cnt  [7 * 200000];             // per-relation dst counts (persist L1->L2)

// ---------------------------------------------------------------------------
// SGEMM: C[M,N] = A[M,K] @ B^T  (B row-major [N,K]; or [K,N] if F_BKN)
// options: relu(A), per-row scale 1/max(cnt,1), +bias[n], accumulate into C
// BM=128, BN=64, BK=16, 256 threads, 8x4 micro-tile
// ---------------------------------------------------------------------------
__global__ void __launch_bounds__(256) sgemm_kernel(
    const float* __restrict__ A, const float* __restrict__ B,
    float* __restrict__ C, const float* __restrict__ bias,
    const int* __restrict__ cnt, int M, int N, int K, int flags)
{
    __shared__ float As[16][128];
    __shared__ float Bs[16][64];
    const int tid = threadIdx.x;
    const int tx = tid & 15;
    const int ty = tid >> 4;
    const int m0 = blockIdx.y * 128;
    const int n0 = blockIdx.x * 64;
    const bool relu = (flags & F_RELU) != 0;

    float acc[8][4];
#pragma unroll
    for (int i = 0; i < 8; i++)
#pragma unroll
        for (int j = 0; j < 4; j++) acc[i][j] = 0.f;

    const int lam = tid >> 1;        // 0..127  (A row within tile)
    const int lak = (tid & 1) * 8;   // 0 or 8  (A k-chunk)

    for (int k0 = 0; k0 < K; k0 += 16) {
        // ---- load A tile (128x16), transposed into As[k][m] ----
        {
            const int gm = m0 + lam;
            float4 a0, a1;
            if (gm < M) {
                const float* p = A + (size_t)gm * K + k0 + lak;
                a0 = *(const float4*)p;
                a1 = *(const float4*)(p + 4);
            } else {
                a0 = make_float4(0.f, 0.f, 0.f, 0.f);
                a1 = a0;
            }
            if (relu) {
                a0.x = fmaxf(a0.x, 0.f); a0.y = fmaxf(a0.y, 0.f);
                a0.z = fmaxf(a0.z, 0.f); a0.w = fmaxf(a0.w, 0.f);
                a1.x = fmaxf(a1.x, 0.f); a1.y = fmaxf(a1.y, 0.f);
                a1.z = fmaxf(a1.z, 0.f); a1.w = fmaxf(a1.w, 0.f);
            }
            As[lak + 0][lam] = a0.x; As[lak + 1][lam] = a0.y;
            As[lak + 2][lam] = a0.z; As[lak + 3][lam] = a0.w;
            As[lak + 4][lam] = a1.x; As[lak + 5][lam] = a1.y;
            As[lak + 6][lam] = a1.z; As[lak + 7][lam] = a1.w;
        }
        // ---- load B tile into Bs[k][n] ----
        if (flags & F_BKN) {
            // B is [K][N] row-major (A @ B)
            const int k = tid >> 4;            // 0..15
            const int nq = (tid & 15) * 4;     // 0..60
            const int gn = n0 + nq;
            float4 b;
            if (gn + 3 < N) {
                b = *(const float4*)(B + (size_t)(k0 + k) * N + gn);
            } else {
                b.x = (gn + 0 < N) ? B[(size_t)(k0 + k) * N + gn + 0] : 0.f;
                b.y = (gn + 1 < N) ? B[(size_t)(k0 + k) * N + gn + 1] : 0.f;
                b.z = (gn + 2 < N) ? B[(size_t)(k0 + k) * N + gn + 2] : 0.f;
                b.w = (gn + 3 < N) ? B[(size_t)(k0 + k) * N + gn + 3] : 0.f;
            }
            *(float4*)&Bs[k][nq] = b;
        } else {
            // B is [N][K] row-major (A @ B^T) -- the weight-matrix case
            const int n = tid >> 2;            // 0..63
            const int kq = (tid & 3) * 4;      // 0..12
            const int gn = n0 + n;
            float4 b = make_float4(0.f, 0.f, 0.f, 0.f);
            if (gn < N) b = *(const float4*)(B + (size_t)gn * K + k0 + kq);
            Bs[kq + 0][n] = b.x; Bs[kq + 1][n] = b.y;
            Bs[kq + 2][n] = b.z; Bs[kq + 3][n] = b.w;
        }
        __syncthreads();

#pragma unroll
        for (int kk = 0; kk < 16; kk++) {
            float4 a0r = *(const float4*)&As[kk][ty * 8];
            float4 a1r = *(const float4*)&As[kk][ty * 8 + 4];
            float4 br  = *(const float4*)&Bs[kk][tx * 4];
            float ar[8] = {a0r.x, a0r.y, a0r.z, a0r.w, a1r.x, a1r.y, a1r.z, a1r.w};
            float bb[4] = {br.x, br.y, br.z, br.w};
#pragma unroll
            for (int i = 0; i < 8; i++)
#pragma unroll
                for (int j = 0; j < 4; j++)
                    acc[i][j] += ar[i] * bb[j];
        }
        __syncthreads();
    }

    float rs[8];
#pragma unroll
    for (int i = 0; i < 8; i++) rs[i] = 1.f;
    if (flags & F_SCALE) {
#pragma unroll
        for (int i = 0; i < 8; i++) {
            int r = m0 + ty * 8 + i;
            if (r < M) { int c = cnt[r]; rs[i] = 1.f / (float)(c > 1 ? c : 1); }
        }
    }
#pragma unroll
    for (int i = 0; i < 8; i++) {
        const int r = m0 + ty * 8 + i;
        if (r >= M) continue;
#pragma unroll
        for (int j = 0; j < 4; j++) {
            const int c = n0 + tx * 4 + j;
            if (c >= N) continue;
            float v = acc[i][j] * rs[i];
            if (flags & F_BIAS) v += bias[c];
            const size_t idx = (size_t)r * N + c;
            if (flags & F_ACCUM) v += C[idx];
            C[idx] = v;
        }
    }
}

// ---------------------------------------------------------------------------
// helpers
// ---------------------------------------------------------------------------
__global__ void fill_f32(float* __restrict__ p, float v, int n)
{
    int i = blockIdx.x * blockDim.x + threadIdx.x;
    const int stride = gridDim.x * blockDim.x;
    for (; i < n; i += stride) p[i] = v;
}

__device__ __forceinline__ void atomicMaxF(float* addr, float v)
{
    if (v >= 0.f) atomicMax((int*)addr, __float_as_int(v));
    else          atomicMin((unsigned int*)addr, __float_as_uint(v));
}

// layer-1 edge scatter: 32 threads per edge, one float4 per thread (128 feats)
__global__ void scatter_l1(const float* __restrict__ basesS,
                           const int* __restrict__ src, const int* __restrict__ dst,
                           float* __restrict__ sum, float* __restrict__ maxb,
                           int* __restrict__ cnt, int E)
{
    const int i = blockIdx.x * blockDim.x + threadIdx.x;
    if (i >= E * 32) return;
    const int e = i >> 5;
    const int c = (i & 31) * 4;
    const int s = src[e], d = dst[e];
    float4 v = *(const float4*)(basesS + (size_t)s * 128 + c);
    atomicAdd((float4*)(sum + (size_t)d * 128 + c), v);
    float* mp = maxb + (size_t)d * 128 + c;
    atomicMaxF(mp + 0, v.x); atomicMaxF(mp + 1, v.y);
    atomicMaxF(mp + 2, v.z); atomicMaxF(mp + 3, v.w);
    if ((i & 31) == 0) atomicAdd(cnt + d, 1);
}

// layer-2 edge scatter: 64 threads per edge (256 feats), relu fused on gather
__global__ void scatter_l2(const float* __restrict__ xsS,
                           const int* __restrict__ src, const int* __restrict__ dst,
                           float* __restrict__ sum, int E)
{
    const int i = blockIdx.x * blockDim.x + threadIdx.x;
    if (i >= E * 64) return;
    const int e = i >> 6;
    const int c = (i & 63) * 4;
    const int s = src[e], d = dst[e];
    float4 v = *(const float4*)(xsS + (size_t)s * 256 + c);
    v.x = fmaxf(v.x, 0.f); v.y = fmaxf(v.y, 0.f);
    v.z = fmaxf(v.z, 0.f); v.w = fmaxf(v.w, 0.f);
    atomicAdd((float4*)(sum + (size_t)d * 256 + c), v);
}

// out1[n, h*32+dd] = sum_b w[n, h*4+b] * bases[n, b*32+dd]
__global__ void combine_root(float* __restrict__ out1, const float* __restrict__ w,
                             const float* __restrict__ bases, int Nn)
{
    const int i = blockIdx.x * blockDim.x + threadIdx.x;
    if (i >= Nn * 256) return;
    const int n = i >> 8;
    const int c = i & 255;
    const int h = c >> 5, dd = c & 31;
    const float* wr = w + (size_t)n * 32 + h * 4;
    const float* br = bases + (size_t)n * 128 + dd;
    float s = wr[0] * br[0] + wr[1] * br[32] + wr[2] * br[64] + wr[3] * br[96];
    out1[(size_t)n * 256 + c] = s;
}

// out1 += einsum over agg = [mean(4x32), max(4x32)], w[n, h*8 + b]
__global__ void combine_rel(float* __restrict__ out1, const float* __restrict__ w,
                            const float* __restrict__ sum, const float* __restrict__ maxb,
                            const int* __restrict__ cnt, int Nn)
{
    const int i = blockIdx.x * blockDim.x + threadIdx.x;
    if (i >= Nn * 256) return;
    const int n = i >> 8;
    const int c = i & 255;
    const int h = c >> 5, dd = c & 31;
    const int ct = cnt[n];
    const float inv = 1.f / (float)(ct > 1 ? ct : 1);
    const float* wr = w + (size_t)n * 64 + h * 8;
    const float* sp = sum + (size_t)n * 128 + dd;
    float s = (wr[0] * sp[0] + wr[1] * sp[32] + wr[2] * sp[64] + wr[3] * sp[96]) * inv;
    if (ct > 0) {
        const float* mp = maxb + (size_t)n * 128 + dd;
        s += wr[4] * mp[0] + wr[5] * mp[32] + wr[6] * mp[64] + wr[7] * mp[96];
    }
    out1[(size_t)n * 256 + c] += s;
}

// ---------------------------------------------------------------------------
// host
// ---------------------------------------------------------------------------
static void gemm(const float* A, const float* B, float* C, const float* bias,
                 const int* cnt, int M, int N, int K, int flags)
{
    dim3 grid((N + 63) / 64, (M + 127) / 128);
    sgemm_kernel<<<grid, 256>>>(A, B, C, bias, cnt, M, N, K, flags);
}

extern "C" void kernel_launch(void* const* d_in, const int* in_sizes, int n_in,
                              void* d_out, int out_size)
{
    const float* x_paper    = (const float*)d_in[0];
    const float* emb_author = (const float*)d_in[1];
    const float* emb_fos    = (const float*)d_in[2];
    const float* emb_inst   = (const float*)d_in[3];
    const float* bases_w1   = (const float*)d_in[4];
    const float* rel_w1     = (const float*)d_in[5];
    const float* rel_b1     = (const float*)d_in[6];
    const float* root_w1    = (const float*)d_in[7];
    const float* root_b1    = (const float*)d_in[8];
    const float* rel_w2     = (const float*)d_in[9];
    const float* root_w2    = (const float*)d_in[10];
    const float* root_b2    = (const float*)d_in[11];
    const int*   src_idx    = (const int*)d_in[12];
    const int*   dst_idx    = (const int*)d_in[13];
    float* out = (float*)d_out;

    static const int NUMSh[4] = {200000, 30000, 5000, 150000};
    static const int OFFh[4]  = {0, 200000, 230000, 235000};
    static const int ST[7] = {0, 2, 0, 3, 3, 3, 1};
    static const int DT[7] = {2, 0, 3, 0, 3, 1, 3};
    const int E = 400000;

    float *bases_p, *out1_p, *w_p, *sum_p, *max_p;
    int* cnt_p;
    cudaGetSymbolAddress((void**)&bases_p, g_bases);
    cudaGetSymbolAddress((void**)&out1_p,  g_out1);
    cudaGetSymbolAddress((void**)&w_p,     g_w);
    cudaGetSymbolAddress((void**)&sum_p,   g_sum);
    cudaGetSymbolAddress((void**)&max_p,   g_max);
    cudaGetSymbolAddress((void**)&cnt_p,   g_cnt);

    const float* xs[4] = {emb_author, emb_fos, emb_inst, x_paper};

    // ======================= layer 1 =======================
    // bases[t] = xs[t] @ bases_w1   (B stored [K=128][N=128])
    for (int t = 0; t < 4; t++) {
        gemm(xs[t], bases_w1, bases_p + (size_t)OFFh[t] * 128,
             nullptr, nullptr, NUMSh[t], 128, 128, F_BKN);
    }
    // root: w = xs[t] @ root_w1[t]^T + b ; out1 = einsum(w, bases)
    for (int t = 0; t < 4; t++) {
        gemm(xs[t], root_w1 + (size_t)t * 32 * 128, w_p, root_b1 + t * 32,
             nullptr, NUMSh[t], 32, 128, F_BIAS);
        const int tot = NUMSh[t] * 256;
        combine_root<<<(tot + 255) / 256, 256>>>(
            out1_p + (size_t)OFFh[t] * 256, w_p,
            bases_p + (size_t)OFFh[t] * 128, NUMSh[t]);
    }
    // relations: segment mean+max of gathered bases, combine via rel_w1
    for (int e = 0; e < 7; e++) {
        const int s = ST[e], d = DT[e], nd = NUMSh[d];
        int* ce = cnt_p + e * 200000;
        fill_f32<<<2048, 256>>>(sum_p, 0.f, nd * 128);
        fill_f32<<<2048, 256>>>(max_p, -INFINITY, nd * 128);
        fill_f32<<<256, 256>>>((float*)ce, 0.f, nd);
        const int tot = E * 32;
        scatter_l1<<<(tot + 255) / 256, 256>>>(
            bases_p + (size_t)OFFh[s] * 128,
            src_idx + (size_t)e * E, dst_idx + (size_t)e * E,
            sum_p, max_p, ce, E);
        gemm(xs[d], rel_w1 + (size_t)e * 64 * 128, w_p, rel_b1 + e * 64,
             nullptr, nd, 64, 128, F_BIAS);
        const int tot2 = nd * 256;
        combine_rel<<<(tot2 + 255) / 256, 256>>>(
            out1_p + (size_t)OFFh[d] * 256, w_p, sum_p, max_p, ce, nd);
    }

    // ======================= layer 2 =======================
    // out2[t] = relu(out1[t]) @ root_w2[t]^T + root_b2[t]
    for (int t = 0; t < 4; t++) {
        gemm(out1_p + (size_t)OFFh[t] * 256, root_w2 + (size_t)t * 349 * 256,
             out + (size_t)OFFh[t] * 349, root_b2 + t * 349, nullptr,
             NUMSh[t], 349, 256, F_RELU | F_BIAS);
    }
    // out2[d] += (segsum(relu(out1[s])[src]) / max(cnt,1)) @ rel_w2[e]^T
    for (int e = 0; e < 7; e++) {
        const int s = ST[e], d = DT[e], nd = NUMSh[d];
        fill_f32<<<4096, 256>>>(sum_p, 0.f, nd * 256);
        const int tot = E * 64;
        scatter_l2<<<(tot + 255) / 256, 256>>>(
            out1_p + (size_t)OFFh[s] * 256,
            src_idx + (size_t)e * E, dst_idx + (size_t)e * E,
            sum_p, E);
        gemm(sum_p, rel_w2 + (size_t)e * 349 * 256,
             out + (size_t)OFFh[d] * 349, nullptr, cnt_p + e * 200000,
             nd, 349, 256, F_SCALE | F_ACCUM);
    }
}

// round 2
// speedup vs baseline: 1.3845x; 1.3845x over previous
#include <cuda_runtime.h>
#include <cuda_fp16.h>
#include <math.h>
#include <stdint.h>

// ---------------------------------------------------------------------------
// REGC: 2-layer hetero GNN.  4 node types [200000,30000,5000,150000], 7 rels,
// E=400000 each. L1: 128->256 (H=8,NB=4,DH=32) mean+max agg. L2: 256->349 mean.
// GEMMs run on tensor cores (HMMA fp16 in / fp32 accum), converted on the fly.
// ---------------------------------------------------------------------------

enum { F_RELU = 1, F_SCALE = 2, F_BIAS = 4, F_ACCUM = 8, F_BKN = 16 };

__device__ float g_bases[(size_t)385000 * 128];
__device__ float g_out1 [(size_t)385000 * 256];
__device__ float g_w    [(size_t)200000 * 64];
__device__ float g_sum  [(size_t)200000 * 256];
__device__ float g_max  [(size_t)200000 * 128];
__device__ int   g_cnt  [7 * 200000];

// ---------------------------------------------------------------------------
// HMMA GEMM: C[M,N] = A[M,K] @ B^T (B=[N][K] row-major; or A@B with B=[K][N]
// if F_BKN).  A,B fp32 in gmem, converted to fp16 in the smem-store stage.
// fp32 accumulate.  Epilogue: relu(A) applied at load; 1/max(cnt,1) row scale;
// +bias[n]; optional accumulate into C.
// BM=128 BN=64 BK=32, 256 threads (8 warps as 4x2), warp tile 32x32.
// ---------------------------------------------------------------------------
__global__ void __launch_bounds__(256) hgemm_kernel(
    const float* __restrict__ A, const float* __restrict__ B,
    float* __restrict__ C, const float* __restrict__ bias,
    const int* __restrict__ cnt, int M, int N, int K, int flags)
{
    __shared__ __half As[128][40];   // [m][k], pad 8 -> 80B row stride
    __shared__ __half Bs[32][72];    // [k][n], pad 8 -> 144B row stride

    const int tid  = threadIdx.x;
    const int lane = tid & 31;
    const int warp = tid >> 5;
    const int wm = (warp & 3) * 32;
    const int wn = (warp >> 2) * 32;
    const int m0 = blockIdx.y * 128;
    const int n0 = blockIdx.x * 64;
    const bool relu = (flags & F_RELU) != 0;

    // A-load mapping: thread -> (row am, k-chunk ak), 4 float4 per iter
    const int am = tid >> 1;
    const int ak = (tid & 1) * 16;
    // B-load mapping (N,K layout): thread -> (n row, k-chunk), 2 float4
    const int bn = tid >> 2;
    const int bk = (tid & 3) * 8;
    // B-load mapping (K,N layout)
    const int bk2 = tid >> 3;
    const int bn2 = (tid & 7) * 8;

    float4 pa[4], pb[2];

    auto load_g = [&](int k0) {
        const int gm = m0 + am;
        if (gm < M) {
            const float* p = A + (size_t)gm * K + k0 + ak;
#pragma unroll
            for (int i = 0; i < 4; i++) pa[i] = *(const float4*)(p + 4 * i);
        } else {
#pragma unroll
            for (int i = 0; i < 4; i++) pa[i] = make_float4(0.f, 0.f, 0.f, 0.f);
        }
        if (relu) {
#pragma unroll
            for (int i = 0; i < 4; i++) {
                pa[i].x = fmaxf(pa[i].x, 0.f); pa[i].y = fmaxf(pa[i].y, 0.f);
                pa[i].z = fmaxf(pa[i].z, 0.f); pa[i].w = fmaxf(pa[i].w, 0.f);
            }
        }
        if (flags & F_BKN) {
#pragma unroll
            for (int i = 0; i < 2; i++) {
                const int gn = n0 + bn2 + 4 * i;
                float4 v = make_float4(0.f, 0.f, 0.f, 0.f);
                if (gn + 3 < N) v = *(const float4*)(B + (size_t)(k0 + bk2) * N + gn);
                else {
                    if (gn + 0 < N) v.x = B[(size_t)(k0 + bk2) * N + gn + 0];
                    if (gn + 1 < N) v.y = B[(size_t)(k0 + bk2) * N + gn + 1];
                    if (gn + 2 < N) v.z = B[(size_t)(k0 + bk2) * N + gn + 2];
                    if (gn + 3 < N) v.w = B[(size_t)(k0 + bk2) * N + gn + 3];
                }
                pb[i] = v;
            }
        } else {
            const int gn = n0 + bn;
            if (gn < N) {
                const float* p = B + (size_t)gn * K + k0 + bk;
                pb[0] = *(const float4*)p;
                pb[1] = *(const float4*)(p + 4);
            } else {
                pb[0] = make_float4(0.f, 0.f, 0.f, 0.f);
                pb[1] = pb[0];
            }
        }
    };

    auto store_s = [&]() {
#pragma unroll
        for (int i = 0; i < 4; i++) {
            *(__half2*)&As[am][ak + 4 * i + 0] = __floats2half2_rn(pa[i].x, pa[i].y);
            *(__half2*)&As[am][ak + 4 * i + 2] = __floats2half2_rn(pa[i].z, pa[i].w);
        }
        if (flags & F_BKN) {
#pragma unroll
            for (int i = 0; i < 2; i++) {
                *(__half2*)&Bs[bk2][bn2 + 4 * i + 0] = __floats2half2_rn(pb[i].x, pb[i].y);
                *(__half2*)&Bs[bk2][bn2 + 4 * i + 2] = __floats2half2_rn(pb[i].z, pb[i].w);
            }
        } else {
#pragma unroll
            for (int i = 0; i < 2; i++) {
                Bs[bk + 4 * i + 0][bn] = __float2half_rn(pb[i].x);
                Bs[bk + 4 * i + 1][bn] = __float2half_rn(pb[i].y);
                Bs[bk + 4 * i + 2][bn] = __float2half_rn(pb[i].z);
                Bs[bk + 4 * i + 3][bn] = __float2half_rn(pb[i].w);
            }
        }
    };

    float acc[2][4][4];
#pragma unroll
    for (int mi = 0; mi < 2; mi++)
#pragma unroll
        for (int nj = 0; nj < 4; nj++)
#pragma unroll
            for (int r = 0; r < 4; r++) acc[mi][nj][r] = 0.f;

    const uint32_t sA = (uint32_t)__cvta_generic_to_shared(&As[0][0]);
    const uint32_t sB = (uint32_t)__cvta_generic_to_shared(&Bs[0][0]);
    // ldmatrix lane address components
    const uint32_t aAddr0 = sA + (uint32_t)((wm + (lane & 15)) * 80 + ((lane >> 4) * 8) * 2);
    const uint32_t bAddr0 = sB + (uint32_t)(((lane & 15)) * 144 + (wn + (lane >> 4) * 8) * 2);

    auto compute = [&]() {
#pragma unroll
        for (int kk = 0; kk < 2; kk++) {
            uint32_t a[2][4], b[4][2];
#pragma unroll
            for (int mi = 0; mi < 2; mi++) {
                uint32_t addr = aAddr0 + (uint32_t)(mi * 16 * 80 + kk * 16 * 2);
                asm volatile("ldmatrix.sync.aligned.m8n8.x4.shared.b16 {%0,%1,%2,%3}, [%4];"
                             : "=r"(a[mi][0]), "=r"(a[mi][1]), "=r"(a[mi][2]), "=r"(a[mi][3])
                             : "r"(addr));
            }
#pragma unroll
            for (int njp = 0; njp < 2; njp++) {
                uint32_t addr = bAddr0 + (uint32_t)(kk * 16 * 144 + njp * 16 * 2);
                asm volatile("ldmatrix.sync.aligned.m8n8.x4.trans.shared.b16 {%0,%1,%2,%3}, [%4];"
                             : "=r"(b[njp * 2][0]), "=r"(b[njp * 2][1]),
                               "=r"(b[njp * 2 + 1][0]), "=r"(b[njp * 2 + 1][1])
                             : "r"(addr));
            }
#pragma unroll
            for (int mi = 0; mi < 2; mi++)
#pragma unroll
                for (int nj = 0; nj < 4; nj++) {
                    asm volatile(
                        "mma.sync.aligned.m16n8k16.row.col.f32.f16.f16.f32 "
                        "{%0,%1,%2,%3}, {%4,%5,%6,%7}, {%8,%9}, {%0,%1,%2,%3};"
                        : "+f"(acc[mi][nj][0]), "+f"(acc[mi][nj][1]),
                          "+f"(acc[mi][nj][2]), "+f"(acc[mi][nj][3])
                        : "r"(a[mi][0]), "r"(a[mi][1]), "r"(a[mi][2]), "r"(a[mi][3]),
                          "r"(b[nj][0]), "r"(b[nj][1]));
                }
        }
    };

    load_g(0);
    store_s();
    __syncthreads();
    for (int k0 = 32; k0 < K; k0 += 32) {
        load_g(k0);
        compute();
        __syncthreads();
        store_s();
        __syncthreads();
    }
    compute();

    // ---- epilogue ----
    float rs[2][2];
#pragma unroll
    for (int mi = 0; mi < 2; mi++)
#pragma unroll
        for (int rp = 0; rp < 2; rp++) {
            rs[mi][rp] = 1.f;
            if (flags & F_SCALE) {
                int r = m0 + wm + mi * 16 + (lane >> 2) + rp * 8;
                if (r < M) { int c = cnt[r]; rs[mi][rp] = 1.f / (float)(c > 1 ? c : 1); }
            }
        }
#pragma unroll
    for (int mi = 0; mi < 2; mi++)
#pragma unroll
        for (int nj = 0; nj < 4; nj++)
#pragma unroll
            for (int r = 0; r < 4; r++) {
                const int rp = r >> 1, cp = r & 1;
                const int row = m0 + wm + mi * 16 + (lane >> 2) + rp * 8;
                const int col = n0 + wn + nj * 8 + (lane & 3) * 2 + cp;
                if (row >= M || col >= N) continue;
                float v = acc[mi][nj][r] * rs[mi][rp];
                if (flags & F_BIAS) v += bias[col];
                const size_t idx = (size_t)row * N + col;
                if (flags & F_ACCUM) v += C[idx];
                C[idx] = v;
            }
}

// ---------------------------------------------------------------------------
// helpers (unchanged, validated in R1)
// ---------------------------------------------------------------------------
__global__ void fill_f32(float* __restrict__ p, float v, int n)
{
    int i = blockIdx.x * blockDim.x + threadIdx.x;
    const int stride = gridDim.x * blockDim.x;
    for (; i < n; i += stride) p[i] = v;
}

__device__ __forceinline__ void atomicMaxF(float* addr, float v)
{
    if (v >= 0.f) atomicMax((int*)addr, __float_as_int(v));
    else          atomicMin((unsigned int*)addr, __float_as_uint(v));
}

__global__ void scatter_l1(const float* __restrict__ basesS,
                           const int* __restrict__ src, const int* __restrict__ dst,
                           float* __restrict__ sum, float* __restrict__ maxb,
                           int* __restrict__ cnt, int E)
{
    const int i = blockIdx.x * blockDim.x + threadIdx.x;
    if (i >= E * 32) return;
    const int e = i >> 5;
    const int c = (i & 31) * 4;
    const int s = src[e], d = dst[e];
    float4 v = *(const float4*)(basesS + (size_t)s * 128 + c);
    atomicAdd((float4*)(sum + (size_t)d * 128 + c), v);
    float* mp = maxb + (size_t)d * 128 + c;
    atomicMaxF(mp + 0, v.x); atomicMaxF(mp + 1, v.y);
    atomicMaxF(mp + 2, v.z); atomicMaxF(mp + 3, v.w);
    if ((i & 31) == 0) atomicAdd(cnt + d, 1);
}

__global__ void scatter_l2(const float* __restrict__ xsS,
                           const int* __restrict__ src, const int* __restrict__ dst,
                           float* __restrict__ sum, int E)
{
    const int i = blockIdx.x * blockDim.x + threadIdx.x;
    if (i >= E * 64) return;
    const int e = i >> 6;
    const int c = (i & 63) * 4;
    const int s = src[e], d = dst[e];
    float4 v = *(const float4*)(xsS + (size_t)s * 256 + c);
    v.x = fmaxf(v.x, 0.f); v.y = fmaxf(v.y, 0.f);
    v.z = fmaxf(v.z, 0.f); v.w = fmaxf(v.w, 0.f);
    atomicAdd((float4*)(sum + (size_t)d * 256 + c), v);
}

__global__ void combine_root(float* __restrict__ out1, const float* __restrict__ w,
                             const float* __restrict__ bases, int Nn)
{
    const int i = blockIdx.x * blockDim.x + threadIdx.x;
    if (i >= Nn * 256) return;
    const int n = i >> 8;
    const int c = i & 255;
    const int h = c >> 5, dd = c & 31;
    const float* wr = w + (size_t)n * 32 + h * 4;
    const float* br = bases + (size_t)n * 128 + dd;
    float s = wr[0] * br[0] + wr[1] * br[32] + wr[2] * br[64] + wr[3] * br[96];
    out1[(size_t)n * 256 + c] = s;
}

__global__ void combine_rel(float* __restrict__ out1, const float* __restrict__ w,
                            const float* __restrict__ sum, const float* __restrict__ maxb,
                            const int* __restrict__ cnt, int Nn)
{
    const int i = blockIdx.x * blockDim.x + threadIdx.x;
    if (i >= Nn * 256) return;
    const int n = i >> 8;
    const int c = i & 255;
    const int h = c >> 5, dd = c & 31;
    const int ct = cnt[n];
    const float inv = 1.f / (float)(ct > 1 ? ct : 1);
    const float* wr = w + (size_t)n * 64 + h * 8;
    const float* sp = sum + (size_t)n * 128 + dd;
    float s = (wr[0] * sp[0] + wr[1] * sp[32] + wr[2] * sp[64] + wr[3] * sp[96]) * inv;
    if (ct > 0) {
        const float* mp = maxb + (size_t)n * 128 + dd;
        s += wr[4] * mp[0] + wr[5] * mp[32] + wr[6] * mp[64] + wr[7] * mp[96];
    }
    out1[(size_t)n * 256 + c] += s;
}

// ---------------------------------------------------------------------------
// host
// ---------------------------------------------------------------------------
static void gemm(const float* A, const float* B, float* C, const float* bias,
                 const int* cnt, int M, int N, int K, int flags)
{
    dim3 grid((N + 63) / 64, (M + 127) / 128);
    hgemm_kernel<<<grid, 256>>>(A, B, C, bias, cnt, M, N, K, flags);
}

extern "C" void kernel_launch(void* const* d_in, const int* in_sizes, int n_in,
                              void* d_out, int out_size)
{
    const float* x_paper    = (const float*)d_in[0];
    const float* emb_author = (const float*)d_in[1];
    const float* emb_fos    = (const float*)d_in[2];
    const float* emb_inst   = (const float*)d_in[3];
    const float* bases_w1   = (const float*)d_in[4];
    const float* rel_w1     = (const float*)d_in[5];
    const float* rel_b1     = (const float*)d_in[6];
    const float* root_w1    = (const float*)d_in[7];
    const float* root_b1    = (const float*)d_in[8];
    const float* rel_w2     = (const float*)d_in[9];
    const float* root_w2    = (const float*)d_in[10];
    const float* root_b2    = (const float*)d_in[11];
    const int*   src_idx    = (const int*)d_in[12];
    const int*   dst_idx    = (const int*)d_in[13];
    float* out = (float*)d_out;

    static const int NUMSh[4] = {200000, 30000, 5000, 150000};
    static const int OFFh[4]  = {0, 200000, 230000, 235000};
    static const int ST[7] = {0, 2, 0, 3, 3, 3, 1};
    static const int DT[7] = {2, 0, 3, 0, 3, 1, 3};
    const int E = 400000;

    float *bases_p, *out1_p, *w_p, *sum_p, *max_p;
    int* cnt_p;
    cudaGetSymbolAddress((void**)&bases_p, g_bases);
    cudaGetSymbolAddress((void**)&out1_p,  g_out1);
    cudaGetSymbolAddress((void**)&w_p,     g_w);
    cudaGetSymbolAddress((void**)&sum_p,   g_sum);
    cudaGetSymbolAddress((void**)&max_p,   g_max);
    cudaGetSymbolAddress((void**)&cnt_p,   g_cnt);

    const float* xs[4] = {emb_author, emb_fos, emb_inst, x_paper};

    // ======================= layer 1 =======================
    for (int t = 0; t < 4; t++) {
        gemm(xs[t], bases_w1, bases_p + (size_t)OFFh[t] * 128,
             nullptr, nullptr, NUMSh[t], 128, 128, F_BKN);
    }
    for (int t = 0; t < 4; t++) {
        gemm(xs[t], root_w1 + (size_t)t * 32 * 128, w_p, root_b1 + t * 32,
             nullptr, NUMSh[t], 32, 128, F_BIAS);
        const int tot = NUMSh[t] * 256;
        combine_root<<<(tot + 255) / 256, 256>>>(
            out1_p + (size_t)OFFh[t] * 256, w_p,
            bases_p + (size_t)OFFh[t] * 128, NUMSh[t]);
    }
    for (int e = 0; e < 7; e++) {
        const int s = ST[e], d = DT[e], nd = NUMSh[d];
        int* ce = cnt_p + e * 200000;
        fill_f32<<<2048, 256>>>(sum_p, 0.f, nd * 128);
        fill_f32<<<2048, 256>>>(max_p, -INFINITY, nd * 128);
        fill_f32<<<256, 256>>>((float*)ce, 0.f, nd);
        const int tot = E * 32;
        scatter_l1<<<(tot + 255) / 256, 256>>>(
            bases_p + (size_t)OFFh[s] * 128,
            src_idx + (size_t)e * E, dst_idx + (size_t)e * E,
            sum_p, max_p, ce, E);
        gemm(xs[d], rel_w1 + (size_t)e * 64 * 128, w_p, rel_b1 + e * 64,
             nullptr, nd, 64, 128, F_BIAS);
        const int tot2 = nd * 256;
        combine_rel<<<(tot2 + 255) / 256, 256>>>(
            out1_p + (size_t)OFFh[d] * 256, w_p, sum_p, max_p, ce, nd);
    }

    // ======================= layer 2 =======================
    for (int t = 0; t < 4; t++) {
        gemm(out1_p + (size_t)OFFh[t] * 256, root_w2 + (size_t)t * 349 * 256,
             out + (size_t)OFFh[t] * 349, root_b2 + t * 349, nullptr,
             NUMSh[t], 349, 256, F_RELU | F_BIAS);
    }
    for (int e = 0; e < 7; e++) {
        const int s = ST[e], d = DT[e], nd = NUMSh[d];
        fill_f32<<<4096, 256>>>(sum_p, 0.f, nd * 256);
        const int tot = E * 64;
        scatter_l2<<<(tot + 255) / 256, 256>>>(
            out1_p + (size_t)OFFh[s] * 256,
            src_idx + (size_t)e * E, dst_idx + (size_t)e * E,
            sum_p, E);
        gemm(sum_p, rel_w2 + (size_t)e * 349 * 256,
             out + (size_t)OFFh[d] * 349, nullptr, cnt_p + e * 200000,
             nd, 349, 256, F_SCALE | F_ACCUM);
    }
}

// round 3
// speedup vs baseline: 1.4457x; 1.0442x over previous
#include <cuda_runtime.h>
#include <cuda_fp16.h>
#include <math.h>
#include <stdint.h>

// ---------------------------------------------------------------------------
// REGC hetero-GNN. Types [author 200000, fos 30000, inst 5000, paper 150000].
// 7 relations x 400000 edges. L1: 128->256 (H=8,NB=4,DH=32) mean+max.
// L2: 256->349 mean. GEMMs on HMMA fp16/f32-acc. Scatter via f32/u32 RED.
// ---------------------------------------------------------------------------

enum { F_RELU = 1, F_SCALE = 2, F_BIAS = 4, F_ACCUM = 8, F_BKN = 16 };

#define E 400000
#define RTOT 885000   // sum of per-relation dst counts

// Persistent scratch (~2.7 GB)
__device__ float    g_bases[(size_t)385000 * 128];
__device__ float    g_out1 [(size_t)385000 * 256];   // stored post-ReLU
__device__ float    g_wroot[(size_t)385000 * 32];
__device__ float    g_wrel [(size_t)RTOT * 64];
__device__ float    g_sum1 [(size_t)RTOT * 128];
__device__ unsigned g_max1 [(size_t)RTOT * 128];     // monotone float keys
__device__ float    g_sum2 [(size_t)RTOT * 256];
__device__ int      g_cnt  [RTOT];

// relation tables (compile-time)
__device__ __forceinline__ void rel_tables(const int*& st, const int*& dt,
                                           const int*& off, const int*& roff)
{
    static __device__ const int ST[7]   = {0, 2, 0, 3, 3, 3, 1};
    static __device__ const int DT[7]   = {2, 0, 3, 0, 3, 1, 3};
    static __device__ const int OFF[4]  = {0, 200000, 230000, 235000};
    static __device__ const int ROFF[7] = {0, 5000, 205000, 355000, 555000, 705000, 735000};
    st = ST; dt = DT; off = OFF; roff = ROFF;
}

__device__ __forceinline__ unsigned fkey(float v)
{
    unsigned b = __float_as_uint(v);
    return (b & 0x80000000u) ? ~b : (b | 0x80000000u);
}
__device__ __forceinline__ float fdec(unsigned k)
{
    return (k & 0x80000000u) ? __uint_as_float(k ^ 0x80000000u) : __uint_as_float(~k);
}

// ---------------------------------------------------------------------------
// HMMA GEMM (validated R2): C[M,N] = A@B^T (B=[N][K]) or A@B (B=[K][N], F_BKN)
// BM=128 BN=64 BK=32, 256 thr, fp16 convert at smem store, f32 accum.
// ---------------------------------------------------------------------------
__global__ void __launch_bounds__(256) hgemm_kernel(
    const float* __restrict__ A, const float* __restrict__ B,
    float* __restrict__ C, const float* __restrict__ bias,
    const int* __restrict__ cnt, int M, int N, int K, int flags)
{
    __shared__ __half As[128][40];
    __shared__ __half Bs[32][72];

    const int tid  = threadIdx.x;
    const int lane = tid & 31;
    const int warp = tid >> 5;
    const int wm = (warp & 3) * 32;
    const int wn = (warp >> 2) * 32;
    const int m0 = blockIdx.y * 128;
    const int n0 = blockIdx.x * 64;
    const bool relu = (flags & F_RELU) != 0;

    const int am = tid >> 1;
    const int ak = (tid & 1) * 16;
    const int bn = tid >> 2;
    const int bk = (tid & 3) * 8;
    const int bk2 = tid >> 3;
    const int bn2 = (tid & 7) * 8;

    float4 pa[4], pb[2];

    auto load_g = [&](int k0) {
        const int gm = m0 + am;
        if (gm < M) {
            const float* p = A + (size_t)gm * K + k0 + ak;
#pragma unroll
            for (int i = 0; i < 4; i++) pa[i] = *(const float4*)(p + 4 * i);
        } else {
#pragma unroll
            for (int i = 0; i < 4; i++) pa[i] = make_float4(0.f, 0.f, 0.f, 0.f);
        }
        if (relu) {
#pragma unroll
            for (int i = 0; i < 4; i++) {
                pa[i].x = fmaxf(pa[i].x, 0.f); pa[i].y = fmaxf(pa[i].y, 0.f);
                pa[i].z = fmaxf(pa[i].z, 0.f); pa[i].w = fmaxf(pa[i].w, 0.f);
            }
        }
        if (flags & F_BKN) {
#pragma unroll
            for (int i = 0; i < 2; i++) {
                const int gn = n0 + bn2 + 4 * i;
                float4 v = make_float4(0.f, 0.f, 0.f, 0.f);
                if (gn + 3 < N) v = *(const float4*)(B + (size_t)(k0 + bk2) * N + gn);
                else {
                    if (gn + 0 < N) v.x = B[(size_t)(k0 + bk2) * N + gn + 0];
                    if (gn + 1 < N) v.y = B[(size_t)(k0 + bk2) * N + gn + 1];
                    if (gn + 2 < N) v.z = B[(size_t)(k0 + bk2) * N + gn + 2];
                    if (gn + 3 < N) v.w = B[(size_t)(k0 + bk2) * N + gn + 3];
                }
                pb[i] = v;
            }
        } else {
            const int gn = n0 + bn;
            if (gn < N) {
                const float* p = B + (size_t)gn * K + k0 + bk;
                pb[0] = *(const float4*)p;
                pb[1] = *(const float4*)(p + 4);
            } else {
                pb[0] = make_float4(0.f, 0.f, 0.f, 0.f);
                pb[1] = pb[0];
            }
        }
    };

    auto store_s = [&]() {
#pragma unroll
        for (int i = 0; i < 4; i++) {
            *(__half2*)&As[am][ak + 4 * i + 0] = __floats2half2_rn(pa[i].x, pa[i].y);
            *(__half2*)&As[am][ak + 4 * i + 2] = __floats2half2_rn(pa[i].z, pa[i].w);
        }
        if (flags & F_BKN) {
#pragma unroll
            for (int i = 0; i < 2; i++) {
                *(__half2*)&Bs[bk2][bn2 + 4 * i + 0] = __floats2half2_rn(pb[i].x, pb[i].y);
                *(__half2*)&Bs[bk2][bn2 + 4 * i + 2] = __floats2half2_rn(pb[i].z, pb[i].w);
            }
        } else {
#pragma unroll
            for (int i = 0; i < 2; i++) {
                Bs[bk + 4 * i + 0][bn] = __float2half_rn(pb[i].x);
                Bs[bk + 4 * i + 1][bn] = __float2half_rn(pb[i].y);
                Bs[bk + 4 * i + 2][bn] = __float2half_rn(pb[i].z);
                Bs[bk + 4 * i + 3][bn] = __float2half_rn(pb[i].w);
            }
        }
    };

    float acc[2][4][4];
#pragma unroll
    for (int mi = 0; mi < 2; mi++)
#pragma unroll
        for (int nj = 0; nj < 4; nj++)
#pragma unroll
            for (int r = 0; r < 4; r++) acc[mi][nj][r] = 0.f;

    const uint32_t sA = (uint32_t)__cvta_generic_to_shared(&As[0][0]);
    const uint32_t sB = (uint32_t)__cvta_generic_to_shared(&Bs[0][0]);
    const uint32_t aAddr0 = sA + (uint32_t)((wm + (lane & 15)) * 80 + ((lane >> 4) * 8) * 2);
    const uint32_t bAddr0 = sB + (uint32_t)(((lane & 15)) * 144 + (wn + (lane >> 4) * 8) * 2);

    auto compute = [&]() {
#pragma unroll
        for (int kk = 0; kk < 2; kk++) {
            uint32_t a[2][4], b[4][2];
#pragma unroll
            for (int mi = 0; mi < 2; mi++) {
                uint32_t addr = aAddr0 + (uint32_t)(mi * 16 * 80 + kk * 16 * 2);
                asm volatile("ldmatrix.sync.aligned.m8n8.x4.shared.b16 {%0,%1,%2,%3}, [%4];"
                             : "=r"(a[mi][0]), "=r"(a[mi][1]), "=r"(a[mi][2]), "=r"(a[mi][3])
                             : "r"(addr));
            }
#pragma unroll
            for (int njp = 0; njp < 2; njp++) {
                uint32_t addr = bAddr0 + (uint32_t)(kk * 16 * 144 + njp * 16 * 2);
                asm volatile("ldmatrix.sync.aligned.m8n8.x4.trans.shared.b16 {%0,%1,%2,%3}, [%4];"
                             : "=r"(b[njp * 2][0]), "=r"(b[njp * 2][1]),
                               "=r"(b[njp * 2 + 1][0]), "=r"(b[njp * 2 + 1][1])
                             : "r"(addr));
            }
#pragma unroll
            for (int mi = 0; mi < 2; mi++)
#pragma unroll
                for (int nj = 0; nj < 4; nj++) {
                    asm volatile(
                        "mma.sync.aligned.m16n8k16.row.col.f32.f16.f16.f32 "
                        "{%0,%1,%2,%3}, {%4,%5,%6,%7}, {%8,%9}, {%0,%1,%2,%3};"
                        : "+f"(acc[mi][nj][0]), "+f"(acc[mi][nj][1]),
                          "+f"(acc[mi][nj][2]), "+f"(acc[mi][nj][3])
                        : "r"(a[mi][0]), "r"(a[mi][1]), "r"(a[mi][2]), "r"(a[mi][3]),
                          "r"(b[nj][0]), "r"(b[nj][1]));
                }
        }
    };

    load_g(0);
    store_s();
    __syncthreads();
    for (int k0 = 32; k0 < K; k0 += 32) {
        load_g(k0);
        compute();
        __syncthreads();
        store_s();
        __syncthreads();
    }
    compute();

    float rs[2][2];
#pragma unroll
    for (int mi = 0; mi < 2; mi++)
#pragma unroll
        for (int rp = 0; rp < 2; rp++) {
            rs[mi][rp] = 1.f;
            if (flags & F_SCALE) {
                int r = m0 + wm + mi * 16 + (lane >> 2) + rp * 8;
                if (r < M) { int c = cnt[r]; rs[mi][rp] = 1.f / (float)(c > 1 ? c : 1); }
            }
        }
#pragma unroll
    for (int mi = 0; mi < 2; mi++)
#pragma unroll
        for (int nj = 0; nj < 4; nj++)
#pragma unroll
            for (int r = 0; r < 4; r++) {
                const int rp = r >> 1, cp = r & 1;
                const int row = m0 + wm + mi * 16 + (lane >> 2) + rp * 8;
                const int col = n0 + wn + nj * 8 + (lane & 3) * 2 + cp;
                if (row >= M || col >= N) continue;
                float v = acc[mi][nj][r] * rs[mi][rp];
                if (flags & F_BIAS) v += bias[col];
                const size_t idx = (size_t)row * N + col;
                if (flags & F_ACCUM) v += C[idx];
                C[idx] = v;
            }
}

// ---------------------------------------------------------------------------
// fused L1 scatter: all 7 relations. blockIdx.y = relation.
// 32 threads/edge, float4 per thread. sum: RED.ADD.v4.f32; max: 4x RED.MAX.u32
// ---------------------------------------------------------------------------
__global__ void __launch_bounds__(256) scatter_l1_all(
    const float* __restrict__ bases, const int* __restrict__ src_idx,
    const int* __restrict__ dst_idx, float* __restrict__ sum1,
    unsigned* __restrict__ max1, int* __restrict__ cnt)
{
    const int *ST, *DT, *OFF, *ROFF;
    rel_tables(ST, DT, OFF, ROFF);
    const int e = blockIdx.y;
    const int i = blockIdx.x * blockDim.x + threadIdx.x;   // < E*32
    const int ed = i >> 5;
    const int c = (i & 31) * 4;
    const int s = src_idx[(size_t)e * E + ed];
    const int d = dst_idx[(size_t)e * E + ed];
    const size_t srow = (size_t)(OFF[ST[e]] + s) * 128 + c;
    const size_t drow = (size_t)(ROFF[e] + d) * 128 + c;
    float4 v = *(const float4*)(bases + srow);
    atomicAdd((float4*)(sum1 + drow), v);
    unsigned* mp = max1 + drow;
    atomicMax(mp + 0, fkey(v.x));
    atomicMax(mp + 1, fkey(v.y));
    atomicMax(mp + 2, fkey(v.z));
    atomicMax(mp + 3, fkey(v.w));
    if ((i & 31) == 0) atomicAdd(cnt + ROFF[e] + d, 1);
}

// ---------------------------------------------------------------------------
// fused L2 scatter: all 7 relations. out1 is already ReLU'd.
// ---------------------------------------------------------------------------
__global__ void __launch_bounds__(256) scatter_l2_all(
    const float* __restrict__ out1, const int* __restrict__ src_idx,
    const int* __restrict__ dst_idx, float* __restrict__ sum2)
{
    const int *ST, *DT, *OFF, *ROFF;
    rel_tables(ST, DT, OFF, ROFF);
    const int e = blockIdx.y;
    const int i = blockIdx.x * blockDim.x + threadIdx.x;   // < E*64
    const int ed = i >> 6;
    const int c = (i & 63) * 4;
    const int s = src_idx[(size_t)e * E + ed];
    const int d = dst_idx[(size_t)e * E + ed];
    float4 v = *(const float4*)(out1 + (size_t)(OFF[ST[e]] + s) * 256 + c);
    atomicAdd((float4*)(sum2 + (size_t)(ROFF[e] + d) * 256 + c), v);
}

// ---------------------------------------------------------------------------
// fused combine for one node type: out1 = relu(root + sum over incoming rels)
// thread per (n, c); c = h*32+dd
// ---------------------------------------------------------------------------
struct RelPtr {
    const float* sum;
    const unsigned* maxk;
    const int* cnt;
    const float* wrel;
};

__global__ void __launch_bounds__(256) combine_type(
    float* __restrict__ out1, const float* __restrict__ wroot,
    const float* __restrict__ bases, int Nn,
    RelPtr r0, RelPtr r1, RelPtr r2, int R)
{
    const int i = blockIdx.x * blockDim.x + threadIdx.x;
    if (i >= Nn * 256) return;
    const int n = i >> 8;
    const int c = i & 255;
    const int h = c >> 5, dd = c & 31;

    const float* wr = wroot + (size_t)n * 32 + h * 4;
    const float* br = bases + (size_t)n * 128 + dd;
    float val = wr[0] * br[0] + wr[1] * br[32] + wr[2] * br[64] + wr[3] * br[96];

    RelPtr rp[3] = {r0, r1, r2};
    for (int r = 0; r < R; r++) {
        const int ct = rp[r].cnt[n];
        const float inv = 1.f / (float)(ct > 1 ? ct : 1);
        const float* w = rp[r].wrel + (size_t)n * 64 + h * 8;
        const float* sp = rp[r].sum + (size_t)n * 128 + dd;
        val += (w[0] * sp[0] + w[1] * sp[32] + w[2] * sp[64] + w[3] * sp[96]) * inv;
        if (ct > 0) {
            const unsigned* mp = rp[r].maxk + (size_t)n * 128 + dd;
            val += w[4] * fdec(mp[0]) + w[5] * fdec(mp[32]) +
                   w[6] * fdec(mp[64]) + w[7] * fdec(mp[96]);
        }
    }
    out1[(size_t)n * 256 + c] = fmaxf(val, 0.f);   // fused ReLU
}

// ---------------------------------------------------------------------------
// host
// ---------------------------------------------------------------------------
static void gemm(const float* A, const float* B, float* C, const float* bias,
                 const int* cnt, int M, int N, int K, int flags)
{
    dim3 grid((N + 63) / 64, (M + 127) / 128);
    hgemm_kernel<<<grid, 256>>>(A, B, C, bias, cnt, M, N, K, flags);
}

extern "C" void kernel_launch(void* const* d_in, const int* in_sizes, int n_in,
                              void* d_out, int out_size)
{
    const float* x_paper    = (const float*)d_in[0];
    const float* emb_author = (const float*)d_in[1];
    const float* emb_fos    = (const float*)d_in[2];
    const float* emb_inst   = (const float*)d_in[3];
    const float* bases_w1   = (const float*)d_in[4];
    const float* rel_w1     = (const float*)d_in[5];
    const float* rel_b1     = (const float*)d_in[6];
    const float* root_w1    = (const float*)d_in[7];
    const float* root_b1    = (const float*)d_in[8];
    const float* rel_w2     = (const float*)d_in[9];
    const float* root_w2    = (const float*)d_in[10];
    const float* root_b2    = (const float*)d_in[11];
    const int*   src_idx    = (const int*)d_in[12];
    const int*   dst_idx    = (const int*)d_in[13];
    float* out = (float*)d_out;

    static const int NUMSh[4] = {200000, 30000, 5000, 150000};
    static const int OFFh[4]  = {0, 200000, 230000, 235000};
    static const int ST[7] = {0, 2, 0, 3, 3, 3, 1};
    static const int DT[7] = {2, 0, 3, 0, 3, 1, 3};
    static const int ROFFh[7] = {0, 5000, 205000, 355000, 555000, 705000, 735000};

    float *bases_p, *out1_p, *wroot_p, *wrel_p, *sum1_p, *sum2_p;
    unsigned* max1_p;
    int* cnt_p;
    cudaGetSymbolAddress((void**)&bases_p, g_bases);
    cudaGetSymbolAddress((void**)&out1_p,  g_out1);
    cudaGetSymbolAddress((void**)&wroot_p, g_wroot);
    cudaGetSymbolAddress((void**)&wrel_p,  g_wrel);
    cudaGetSymbolAddress((void**)&sum1_p,  g_sum1);
    cudaGetSymbolAddress((void**)&max1_p,  g_max1);
    cudaGetSymbolAddress((void**)&sum2_p,  g_sum2);
    cudaGetSymbolAddress((void**)&cnt_p,   g_cnt);

    const float* xs[4] = {emb_author, emb_fos, emb_inst, x_paper};

    // ---- clear aggregation arenas (memset nodes; ~1.8 GB total) ----
    cudaMemsetAsync(sum1_p, 0, (size_t)RTOT * 128 * sizeof(float));
    cudaMemsetAsync(max1_p, 0, (size_t)RTOT * 128 * sizeof(unsigned));  // key sentinel
    cudaMemsetAsync(sum2_p, 0, (size_t)RTOT * 256 * sizeof(float));
    cudaMemsetAsync(cnt_p,  0, (size_t)RTOT * sizeof(int));

    // ======================= layer 1 GEMMs =======================
    for (int t = 0; t < 4; t++)
        gemm(xs[t], bases_w1, bases_p + (size_t)OFFh[t] * 128,
             nullptr, nullptr, NUMSh[t], 128, 128, F_BKN);
    for (int t = 0; t < 4; t++)
        gemm(xs[t], root_w1 + (size_t)t * 32 * 128, wroot_p + (size_t)OFFh[t] * 32,
             root_b1 + t * 32, nullptr, NUMSh[t], 32, 128, F_BIAS);
    for (int e = 0; e < 7; e++)
        gemm(xs[DT[e]], rel_w1 + (size_t)e * 64 * 128, wrel_p + (size_t)ROFFh[e] * 64,
             rel_b1 + e * 64, nullptr, NUMSh[DT[e]], 64, 128, F_BIAS);

    // ---- fused L1 scatter (all relations) ----
    {
        dim3 grid(E * 32 / 256, 7);
        scatter_l1_all<<<grid, 256>>>(bases_p, src_idx, dst_idx, sum1_p, max1_p, cnt_p);
    }

    // ---- fused combine per node type (writes ReLU'd out1 once) ----
    for (int t = 0; t < 4; t++) {
        RelPtr rp[3];
        int R = 0;
        for (int e = 0; e < 7; e++) {
            if (DT[e] != t) continue;
            rp[R].sum  = sum1_p + (size_t)ROFFh[e] * 128;
            rp[R].maxk = max1_p + (size_t)ROFFh[e] * 128;
            rp[R].cnt  = cnt_p + ROFFh[e];
            rp[R].wrel = wrel_p + (size_t)ROFFh[e] * 64;
            R++;
        }
        for (int r = R; r < 3; r++) rp[r] = rp[0];
        const int tot = NUMSh[t] * 256;
        combine_type<<<(tot + 255) / 256, 256>>>(
            out1_p + (size_t)OFFh[t] * 256, wroot_p + (size_t)OFFh[t] * 32,
            bases_p + (size_t)OFFh[t] * 128, NUMSh[t], rp[0], rp[1], rp[2], R);
    }

    // ======================= layer 2 =======================
    // fused L2 scatter (out1 already ReLU'd)
    {
        dim3 grid(E * 64 / 256, 7);
        scatter_l2_all<<<grid, 256>>>(out1_p, src_idx, dst_idx, sum2_p);
    }
    // root GEMMs
    for (int t = 0; t < 4; t++)
        gemm(out1_p + (size_t)OFFh[t] * 256, root_w2 + (size_t)t * 349 * 256,
             out + (size_t)OFFh[t] * 349, root_b2 + t * 349, nullptr,
             NUMSh[t], 349, 256, F_BIAS);
    // relation GEMMs (mean scale in epilogue, accumulate into out)
    for (int e = 0; e < 7; e++)
        gemm(sum2_p + (size_t)ROFFh[e] * 256, rel_w2 + (size_t)e * 349 * 256,
             out + (size_t)OFFh[DT[e]] * 349, nullptr, cnt_p + ROFFh[e],
             NUMSh[DT[e]], 349, 256, F_SCALE | F_ACCUM);
}

// round 5
// speedup vs baseline: 1.8816x; 1.3015x over previous
#include <cuda_runtime.h>
#include <cuda_fp16.h>
#include <math.h>
#include <stdint.h>

// ---------------------------------------------------------------------------
// REGC hetero-GNN. Types [author 200000, fos 30000, inst 5000, paper 150000].
// 7 relations x 400000 edges. L1: 128->256 (H=8,NB=4,DH=32) mean+max.
// L2: 256->349 mean. GEMMs on HMMA. Aggregation via CSR (counting sort),
// NO atomics on feature data.
// ---------------------------------------------------------------------------

enum { F_RELU = 1, F_SCALE = 2, F_BIAS = 4, F_ACCUM = 8, F_BKN = 16 };

#define E     400000
#define RTOT  885000      // sum over relations of n_dst
#define TOTE  2800000     // 7 * E

// Persistent scratch
__device__ float g_bases[(size_t)385000 * 128];
__device__ float g_out1 [(size_t)385000 * 256];   // post-ReLU
__device__ float g_wroot[(size_t)385000 * 32];
__device__ float g_wrel [(size_t)RTOT * 64];
__device__ float g_sum2 [(size_t)RTOT * 256];     // L2 mean rows
__device__ int   g_cnt   [RTOT];
__device__ int   g_rowptr[RTOT + 1];
__device__ int   g_cursor[RTOT];
__device__ int   g_ebuf  [TOTE];                  // global source row ids

__device__ __constant__ int c_ST[7]   = {0, 2, 0, 3, 3, 3, 1};
__device__ __constant__ int c_OFF[4]  = {0, 200000, 230000, 235000};
__device__ __constant__ int c_ROFF[7] = {0, 5000, 205000, 355000, 555000, 705000, 735000};

// ---------------------------------------------------------------------------
// HMMA GEMM (validated R2/R3)
// ---------------------------------------------------------------------------
__global__ void __launch_bounds__(256) hgemm_kernel(
    const float* __restrict__ A, const float* __restrict__ B,
    float* __restrict__ C, const float* __restrict__ bias,
    int M, int N, int K, int flags)
{
    __shared__ __half As[128][40];
    __shared__ __half Bs[32][72];

    const int tid  = threadIdx.x;
    const int lane = tid & 31;
    const int warp = tid >> 5;
    const int wm = (warp & 3) * 32;
    const int wn = (warp >> 2) * 32;
    const int m0 = blockIdx.y * 128;
    const int n0 = blockIdx.x * 64;
    const bool relu = (flags & F_RELU) != 0;

    const int am = tid >> 1;
    const int ak = (tid & 1) * 16;
    const int bn = tid >> 2;
    const int bk = (tid & 3) * 8;
    const int bk2 = tid >> 3;
    const int bn2 = (tid & 7) * 8;

    float4 pa[4], pb[2];

    auto load_g = [&](int k0) {
        const int gm = m0 + am;
        if (gm < M) {
            const float* p = A + (size_t)gm * K + k0 + ak;
#pragma unroll
            for (int i = 0; i < 4; i++) pa[i] = *(const float4*)(p + 4 * i);
        } else {
#pragma unroll
            for (int i = 0; i < 4; i++) pa[i] = make_float4(0.f, 0.f, 0.f, 0.f);
        }
        if (relu) {
#pragma unroll
            for (int i = 0; i < 4; i++) {
                pa[i].x = fmaxf(pa[i].x, 0.f); pa[i].y = fmaxf(pa[i].y, 0.f);
                pa[i].z = fmaxf(pa[i].z, 0.f); pa[i].w = fmaxf(pa[i].w, 0.f);
            }
        }
        if (flags & F_BKN) {
#pragma unroll
            for (int i = 0; i < 2; i++) {
                const int gn = n0 + bn2 + 4 * i;
                float4 v = make_float4(0.f, 0.f, 0.f, 0.f);
                if (gn + 3 < N) v = *(const float4*)(B + (size_t)(k0 + bk2) * N + gn);
                else {
                    if (gn + 0 < N) v.x = B[(size_t)(k0 + bk2) * N + gn + 0];
                    if (gn + 1 < N) v.y = B[(size_t)(k0 + bk2) * N + gn + 1];
                    if (gn + 2 < N) v.z = B[(size_t)(k0 + bk2) * N + gn + 2];
                    if (gn + 3 < N) v.w = B[(size_t)(k0 + bk2) * N + gn + 3];
                }
                pb[i] = v;
            }
        } else {
            const int gn = n0 + bn;
            if (gn < N) {
                const float* p = B + (size_t)gn * K + k0 + bk;
                pb[0] = *(const float4*)p;
                pb[1] = *(const float4*)(p + 4);
            } else {
                pb[0] = make_float4(0.f, 0.f, 0.f, 0.f);
                pb[1] = pb[0];
            }
        }
    };

    auto store_s = [&]() {
#pragma unroll
        for (int i = 0; i < 4; i++) {
            *(__half2*)&As[am][ak + 4 * i + 0] = __floats2half2_rn(pa[i].x, pa[i].y);
            *(__half2*)&As[am][ak + 4 * i + 2] = __floats2half2_rn(pa[i].z, pa[i].w);
        }
        if (flags & F_BKN) {
#pragma unroll
            for (int i = 0; i < 2; i++) {
                *(__half2*)&Bs[bk2][bn2 + 4 * i + 0] = __floats2half2_rn(pb[i].x, pb[i].y);
                *(__half2*)&Bs[bk2][bn2 + 4 * i + 2] = __floats2half2_rn(pb[i].z, pb[i].w);
            }
        } else {
#pragma unroll
            for (int i = 0; i < 2; i++) {
                Bs[bk + 4 * i + 0][bn] = __float2half_rn(pb[i].x);
                Bs[bk + 4 * i + 1][bn] = __float2half_rn(pb[i].y);
                Bs[bk + 4 * i + 2][bn] = __float2half_rn(pb[i].z);
                Bs[bk + 4 * i + 3][bn] = __float2half_rn(pb[i].w);
            }
        }
    };

    float acc[2][4][4];
#pragma unroll
    for (int mi = 0; mi < 2; mi++)
#pragma unroll
        for (int nj = 0; nj < 4; nj++)
#pragma unroll
            for (int r = 0; r < 4; r++) acc[mi][nj][r] = 0.f;

    const uint32_t sA = (uint32_t)__cvta_generic_to_shared(&As[0][0]);
    const uint32_t sB = (uint32_t)__cvta_generic_to_shared(&Bs[0][0]);
    const uint32_t aAddr0 = sA + (uint32_t)((wm + (lane & 15)) * 80 + ((lane >> 4) * 8) * 2);
    const uint32_t bAddr0 = sB + (uint32_t)(((lane & 15)) * 144 + (wn + (lane >> 4) * 8) * 2);

    auto compute = [&]() {
#pragma unroll
        for (int kk = 0; kk < 2; kk++) {
            uint32_t a[2][4], b[4][2];
#pragma unroll
            for (int mi = 0; mi < 2; mi++) {
                uint32_t addr = aAddr0 + (uint32_t)(mi * 16 * 80 + kk * 16 * 2);
                asm volatile("ldmatrix.sync.aligned.m8n8.x4.shared.b16 {%0,%1,%2,%3}, [%4];"
                             : "=r"(a[mi][0]), "=r"(a[mi][1]), "=r"(a[mi][2]), "=r"(a[mi][3])
                             : "r"(addr));
            }
#pragma unroll
            for (int njp = 0; njp < 2; njp++) {
                uint32_t addr = bAddr0 + (uint32_t)(kk * 16 * 144 + njp * 16 * 2);
                asm volatile("ldmatrix.sync.aligned.m8n8.x4.trans.shared.b16 {%0,%1,%2,%3}, [%4];"
                             : "=r"(b[njp * 2][0]), "=r"(b[njp * 2][1]),
                               "=r"(b[njp * 2 + 1][0]), "=r"(b[njp * 2 + 1][1])
                             : "r"(addr));
            }
#pragma unroll
            for (int mi = 0; mi < 2; mi++)
#pragma unroll
                for (int nj = 0; nj < 4; nj++) {
                    asm volatile(
                        "mma.sync.aligned.m16n8k16.row.col.f32.f16.f16.f32 "
                        "{%0,%1,%2,%3}, {%4,%5,%6,%7}, {%8,%9}, {%0,%1,%2,%3};"
                        : "+f"(acc[mi][nj][0]), "+f"(acc[mi][nj][1]),
                          "+f"(acc[mi][nj][2]), "+f"(acc[mi][nj][3])
                        : "r"(a[mi][0]), "r"(a[mi][1]), "r"(a[mi][2]), "r"(a[mi][3]),
                          "r"(b[nj][0]), "r"(b[nj][1]));
                }
        }
    };

    load_g(0);
    store_s();
    __syncthreads();
    for (int k0 = 32; k0 < K; k0 += 32) {
        load_g(k0);
        compute();
        __syncthreads();
        store_s();
        __syncthreads();
    }
    compute();

#pragma unroll
    for (int mi = 0; mi < 2; mi++)
#pragma unroll
        for (int nj = 0; nj < 4; nj++)
#pragma unroll
            for (int r = 0; r < 4; r++) {
                const int rp = r >> 1, cp = r & 1;
                const int row = m0 + wm + mi * 16 + (lane >> 2) + rp * 8;
                const int col = n0 + wn + nj * 8 + (lane & 3) * 2 + cp;
                if (row >= M || col >= N) continue;
                float v = acc[mi][nj][r];
                if (flags & F_BIAS) v += bias[col];
                const size_t idx = (size_t)row * N + col;
                if (flags & F_ACCUM) v += C[idx];
                C[idx] = v;
            }
}

// ---------------------------------------------------------------------------
// CSR build
// ---------------------------------------------------------------------------
__global__ void count_kernel(const int* __restrict__ dst_idx)
{
    const int e = blockIdx.y;
    const int i = blockIdx.x * blockDim.x + threadIdx.x;
    if (i >= E) return;
    atomicAdd(&g_cnt[c_ROFF[e] + dst_idx[(size_t)e * E + i]], 1);
}

// 2048 items per block exclusive scan; partial to g_rowptr, block sums to bsum
__device__ int g_bsum[512];

__global__ void __launch_bounds__(256) scan1_kernel()
{
    __shared__ int s[256];
    const int tid = threadIdx.x;
    const int tbase = blockIdx.x * 2048 + tid * 8;
    int vals[8];
    int tsum = 0;
#pragma unroll
    for (int j = 0; j < 8; j++) {
        int v = (tbase + j < RTOT) ? g_cnt[tbase + j] : 0;
        vals[j] = tsum;
        tsum += v;
    }
    s[tid] = tsum;
    __syncthreads();
    for (int off = 1; off < 256; off <<= 1) {
        int t = (tid >= off) ? s[tid - off] : 0;
        __syncthreads();
        s[tid] += t;
        __syncthreads();
    }
    const int texcl = (tid > 0) ? s[tid - 1] : 0;
    if (tid == 255) g_bsum[blockIdx.x] = s[255];
#pragma unroll
    for (int j = 0; j < 8; j++)
        if (tbase + j < RTOT) g_rowptr[tbase + j] = vals[j] + texcl;
}

__global__ void __launch_bounds__(512) scan2_kernel(int nb)
{
    __shared__ int s[512];
    const int tid = threadIdx.x;
    s[tid] = (tid < nb) ? g_bsum[tid] : 0;
    __syncthreads();
    for (int off = 1; off < 512; off <<= 1) {
        int t = (tid >= off) ? s[tid - off] : 0;
        __syncthreads();
        s[tid] += t;
        __syncthreads();
    }
    g_bsum[tid] = (tid > 0) ? s[tid - 1] : 0;
}

__global__ void scan3_kernel()
{
    const int i = blockIdx.x * blockDim.x + threadIdx.x;
    if (i < RTOT) {
        int v = g_rowptr[i] + g_bsum[i >> 11];
        g_rowptr[i] = v;
        g_cursor[i] = v;
    } else if (i == RTOT) {
        g_rowptr[RTOT] = TOTE;
    }
}

__global__ void fill_kernel(const int* __restrict__ src_idx,
                            const int* __restrict__ dst_idx)
{
    const int e = blockIdx.y;
    const int i = blockIdx.x * blockDim.x + threadIdx.x;
    if (i >= E) return;
    const int d = dst_idx[(size_t)e * E + i];
    const int s = src_idx[(size_t)e * E + i];
    const int pos = atomicAdd(&g_cursor[c_ROFF[e] + d], 1);
    g_ebuf[pos] = c_OFF[c_ST[e]] + s;   // global source row
}

// ---------------------------------------------------------------------------
// L1 fused: per-warp dst node. agg (mean+max over CSR edges) + root + rels,
// ReLU, single out1 write. roff[r] = global row offset of relation r's rows.
// ---------------------------------------------------------------------------
__global__ void __launch_bounds__(256) l1_fused_kernel(
    float* __restrict__ out1, const float* __restrict__ wroot,
    int tOff, int Nn, int roff0, int roff1, int roff2, int R)
{
    __shared__ float smb[8][128];
    __shared__ float sma[8][256];

    const int warp = threadIdx.x >> 5;
    const int lane = threadIdx.x & 31;
    const int n = blockIdx.x * 8 + warp;
    if (n >= Nn) return;
    const int c4 = lane * 4;
    const int h  = lane >> 2;           // head for this lane's 8 outputs

    // bases row -> smem
    float4 b4 = *(const float4*)(g_bases + (size_t)(tOff + n) * 128 + c4);
    *(float4*)&smb[warp][c4] = b4;
    __syncwarp();

    // root contribution
    float val[8];
    {
        const float4 w = *(const float4*)(wroot + (size_t)n * 32 + h * 4);
#pragma unroll
        for (int j = 0; j < 8; j++) {
            const int dd = (lane * 8 + j) & 31;
            val[j] = w.x * smb[warp][dd] + w.y * smb[warp][32 + dd] +
                     w.z * smb[warp][64 + dd] + w.w * smb[warp][96 + dd];
        }
    }

    const int roffs[3] = {roff0, roff1, roff2};
    for (int r = 0; r < R; r++) {
        const int g = roffs[r] + n;
        const int rs = g_rowptr[g];
        const int re = g_rowptr[g + 1];
        const int ct = re - rs;
        float4 s4 = make_float4(0.f, 0.f, 0.f, 0.f);
        float4 m4 = make_float4(-INFINITY, -INFINITY, -INFINITY, -INFINITY);
        for (int k = rs; k < re; k++) {
            const float4 v = *(const float4*)(g_bases + (size_t)g_ebuf[k] * 128 + c4);
            s4.x += v.x; s4.y += v.y; s4.z += v.z; s4.w += v.w;
            m4.x = fmaxf(m4.x, v.x); m4.y = fmaxf(m4.y, v.y);
            m4.z = fmaxf(m4.z, v.z); m4.w = fmaxf(m4.w, v.w);
        }
        const float inv = 1.f / (float)(ct > 1 ? ct : 1);
        s4.x *= inv; s4.y *= inv; s4.z *= inv; s4.w *= inv;
        if (ct == 0) m4 = make_float4(0.f, 0.f, 0.f, 0.f);
        *(float4*)&sma[warp][c4]       = s4;   // mean at [0,128)
        *(float4*)&sma[warp][128 + c4] = m4;   // max  at [128,256)
        __syncwarp();
        const float4 wa = *(const float4*)(g_wrel + (size_t)g * 64 + h * 8);
        const float4 wb = *(const float4*)(g_wrel + (size_t)g * 64 + h * 8 + 4);
        const float wv[8] = {wa.x, wa.y, wa.z, wa.w, wb.x, wb.y, wb.z, wb.w};
#pragma unroll
        for (int j = 0; j < 8; j++) {
            const int dd = (lane * 8 + j) & 31;
#pragma unroll
            for (int b = 0; b < 8; b++)
                val[j] += wv[b] * sma[warp][b * 32 + dd];
        }
        __syncwarp();
    }

    float* orow = out1 + (size_t)n * 256 + lane * 8;
    float4 o0 = make_float4(fmaxf(val[0], 0.f), fmaxf(val[1], 0.f),
                            fmaxf(val[2], 0.f), fmaxf(val[3], 0.f));
    float4 o1 = make_float4(fmaxf(val[4], 0.f), fmaxf(val[5], 0.f),
                            fmaxf(val[6], 0.f), fmaxf(val[7], 0.f));
    *(float4*)orow = o0;
    *(float4*)(orow + 4) = o1;
}

// ---------------------------------------------------------------------------
// L2 aggregation: warp per global (rel,dst) row; writes MEAN row once.
// ---------------------------------------------------------------------------
__global__ void __launch_bounds__(256) l2_agg_kernel()
{
    const int warp = threadIdx.x >> 5;
    const int lane = threadIdx.x & 31;
    const int g = blockIdx.x * 8 + warp;
    if (g >= RTOT) return;
    const int c4 = lane * 4;
    const int rs = g_rowptr[g];
    const int re = g_rowptr[g + 1];
    const int ct = re - rs;
    float4 a0 = make_float4(0.f, 0.f, 0.f, 0.f);
    float4 a1 = a0;
    for (int k = rs; k < re; k++) {
        const float* row = g_out1 + (size_t)g_ebuf[k] * 256;
        const float4 v0 = *(const float4*)(row + c4);
        const float4 v1 = *(const float4*)(row + 128 + c4);
        a0.x += v0.x; a0.y += v0.y; a0.z += v0.z; a0.w += v0.w;
        a1.x += v1.x; a1.y += v1.y; a1.z += v1.z; a1.w += v1.w;
    }
    const float inv = 1.f / (float)(ct > 1 ? ct : 1);
    a0.x *= inv; a0.y *= inv; a0.z *= inv; a0.w *= inv;
    a1.x *= inv; a1.y *= inv; a1.z *= inv; a1.w *= inv;
    float* o = g_sum2 + (size_t)g * 256;
    *(float4*)(o + c4) = a0;
    *(float4*)(o + 128 + c4) = a1;
}

// ---------------------------------------------------------------------------
// host
// ---------------------------------------------------------------------------
static void gemm(const float* A, const float* B, float* C, const float* bias,
                 int M, int N, int K, int flags)
{
    dim3 grid((N + 63) / 64, (M + 127) / 128);
    hgemm_kernel<<<grid, 256>>>(A, B, C, bias, M, N, K, flags);
}

extern "C" void kernel_launch(void* const* d_in, const int* in_sizes, int n_in,
                              void* d_out, int out_size)
{
    const float* x_paper    = (const float*)d_in[0];
    const float* emb_author = (const float*)d_in[1];
    const float* emb_fos    = (const float*)d_in[2];
    const float* emb_inst   = (const float*)d_in[3];
    const float* bases_w1   = (const float*)d_in[4];
    const float* rel_w1     = (const float*)d_in[5];
    const float* rel_b1     = (const float*)d_in[6];
    const float* root_w1    = (const float*)d_in[7];
    const float* root_b1    = (const float*)d_in[8];
    const float* rel_w2     = (const float*)d_in[9];
    const float* root_w2    = (const float*)d_in[10];
    const float* root_b2    = (const float*)d_in[11];
    const int*   src_idx    = (const int*)d_in[12];
    const int*   dst_idx    = (const int*)d_in[13];
    float* out = (float*)d_out;

    static const int NUMSh[4] = {200000, 30000, 5000, 150000};
    static const int OFFh[4]  = {0, 200000, 230000, 235000};
    static const int DT[7] = {2, 0, 3, 0, 3, 1, 3};
    static const int ROFFh[7] = {0, 5000, 205000, 355000, 555000, 705000, 735000};

    float *bases_p, *out1_p, *wroot_p, *wrel_p, *sum2_p;
    int* cnt_p;
    cudaGetSymbolAddress((void**)&bases_p, g_bases);
    cudaGetSymbolAddress((void**)&out1_p,  g_out1);
    cudaGetSymbolAddress((void**)&wroot_p, g_wroot);
    cudaGetSymbolAddress((void**)&wrel_p,  g_wrel);
    cudaGetSymbolAddress((void**)&sum2_p,  g_sum2);
    cudaGetSymbolAddress((void**)&cnt_p,   g_cnt);

    const float* xs[4] = {emb_author, emb_fos, emb_inst, x_paper};

    // ---- CSR build (shared by both layers) ----
    cudaMemsetAsync(cnt_p, 0, (size_t)RTOT * sizeof(int));
    {
        dim3 grid((E + 255) / 256, 7);
        count_kernel<<<grid, 256>>>(dst_idx);
    }
    scan1_kernel<<<(RTOT + 2047) / 2048, 256>>>();
    scan2_kernel<<<1, 512>>>((RTOT + 2047) / 2048);
    scan3_kernel<<<(RTOT + 1 + 255) / 256, 256>>>();
    {
        dim3 grid((E + 255) / 256, 7);
        fill_kernel<<<grid, 256>>>(src_idx, dst_idx);
    }

    // ---- layer-1 GEMMs ----
    for (int t = 0; t < 4; t++)
        gemm(xs[t], bases_w1, bases_p + (size_t)OFFh[t] * 128,
             nullptr, NUMSh[t], 128, 128, F_BKN);
    for (int t = 0; t < 4; t++)
        gemm(xs[t], root_w1 + (size_t)t * 32 * 128, wroot_p + (size_t)OFFh[t] * 32,
             root_b1 + t * 32, NUMSh[t], 32, 128, F_BIAS);
    for (int e = 0; e < 7; e++)
        gemm(xs[DT[e]], rel_w1 + (size_t)e * 64 * 128, wrel_p + (size_t)ROFFh[e] * 64,
             rel_b1 + e * 64, NUMSh[DT[e]], 64, 128, F_BIAS);

    // ---- layer-1 fused aggregate+combine (per node type) ----
    for (int t = 0; t < 4; t++) {
        int ro[3] = {0, 0, 0};
        int R = 0;
        for (int e = 0; e < 7; e++)
            if (DT[e] == t) ro[R++] = ROFFh[e];
        l1_fused_kernel<<<(NUMSh[t] + 7) / 8, 256>>>(
            out1_p + (size_t)OFFh[t] * 256, wroot_p + (size_t)OFFh[t] * 32,
            OFFh[t], NUMSh[t], ro[0], ro[1], ro[2], R);
    }

    // ---- layer-2 aggregation (mean rows, no atomics) ----
    l2_agg_kernel<<<(RTOT + 7) / 8, 256>>>();

    // ---- layer-2 GEMMs ----
    for (int t = 0; t < 4; t++)
        gemm(out1_p + (size_t)OFFh[t] * 256, root_w2 + (size_t)t * 349 * 256,
             out + (size_t)OFFh[t] * 349, root_b2 + t * 349,
             NUMSh[t], 349, 256, F_BIAS);
    for (int e = 0; e < 7; e++)
        gemm(sum2_p + (size_t)ROFFh[e] * 256, rel_w2 + (size_t)e * 349 * 256,
             out + (size_t)OFFh[DT[e]] * 349, nullptr,
             NUMSh[DT[e]], 349, 256, F_ACCUM);
}

// round 6
// speedup vs baseline: 3.6003x; 1.9134x over previous
#include <cuda_runtime.h>
#include <cuda_fp16.h>
#include <math.h>
#include <stdint.h>

// ---------------------------------------------------------------------------
// REGC hetero-GNN. Types [author 200000, fos 30000, inst 5000, paper 150000].
// 7 relations x 400000 edges. L1: 128->256 (H=8,NB=4,DH=32) mean+max.
// L2: 256->349 mean. HMMA GEMMs; CSR aggregation (no feature atomics);
// fp16 storage for all intermediates; layer-2 as one multi-segment GEMM
// per destination type (out written exactly once).
// ---------------------------------------------------------------------------

enum { F_BIAS = 4, F_BKN = 16, F_CHALF = 32 };

#define E     400000
#define RTOT  885000
#define TOTE  2800000

__device__ __half g_bases[(size_t)385000 * 128];
__device__ __half g_out1 [(size_t)385000 * 256];   // post-ReLU
__device__ __half g_wroot[(size_t)385000 * 32];
__device__ __half g_wrel [(size_t)RTOT * 64];
__device__ __half g_sum2 [(size_t)RTOT * 256];     // L2 mean rows
__device__ int    g_cnt   [RTOT];
__device__ int    g_rowptr[RTOT + 1];
__device__ int    g_cursor[RTOT];
__device__ int    g_ebuf  [TOTE];
__device__ int    g_bsum  [512];

__device__ __constant__ int c_ST[7]   = {0, 2, 0, 3, 3, 3, 1};
__device__ __constant__ int c_OFF[4]  = {0, 200000, 230000, 235000};
__device__ __constant__ int c_ROFF[7] = {0, 5000, 205000, 355000, 555000, 705000, 735000};

// ---------------------------------------------------------------------------
// HMMA GEMM, f32 A/B inputs: C = A@B^T (B=[N][K]) or A@B (B=[K][N], F_BKN).
// C store f32 or fp16 (F_CHALF). BM=128 BN=64 BK=32, 256 threads.
// ---------------------------------------------------------------------------
__global__ void __launch_bounds__(256) hgemm_kernel(
    const float* __restrict__ A, const float* __restrict__ B,
    void* __restrict__ C, const float* __restrict__ bias,
    int M, int N, int K, int flags)
{
    __shared__ __half As[128][40];
    __shared__ __half Bs[32][72];

    const int tid  = threadIdx.x;
    const int lane = tid & 31;
    const int warp = tid >> 5;
    const int wm = (warp & 3) * 32;
    const int wn = (warp >> 2) * 32;
    const int m0 = blockIdx.y * 128;
    const int n0 = blockIdx.x * 64;

    const int am = tid >> 1;
    const int ak = (tid & 1) * 16;
    const int bn = tid >> 2;
    const int bk = (tid & 3) * 8;
    const int bk2 = tid >> 3;
    const int bn2 = (tid & 7) * 8;

    float4 pa[4], pb[2];

    auto load_g = [&](int k0) {
        const int gm = m0 + am;
        if (gm < M) {
            const float* p = A + (size_t)gm * K + k0 + ak;
#pragma unroll
            for (int i = 0; i < 4; i++) pa[i] = *(const float4*)(p + 4 * i);
        } else {
#pragma unroll
            for (int i = 0; i < 4; i++) pa[i] = make_float4(0.f, 0.f, 0.f, 0.f);
        }
        if (flags & F_BKN) {
#pragma unroll
            for (int i = 0; i < 2; i++) {
                const int gn = n0 + bn2 + 4 * i;
                float4 v = make_float4(0.f, 0.f, 0.f, 0.f);
                if (gn + 3 < N) v = *(const float4*)(B + (size_t)(k0 + bk2) * N + gn);
                else {
                    if (gn + 0 < N) v.x = B[(size_t)(k0 + bk2) * N + gn + 0];
                    if (gn + 1 < N) v.y = B[(size_t)(k0 + bk2) * N + gn + 1];
                    if (gn + 2 < N) v.z = B[(size_t)(k0 + bk2) * N + gn + 2];
                    if (gn + 3 < N) v.w = B[(size_t)(k0 + bk2) * N + gn + 3];
                }
                pb[i] = v;
            }
        } else {
            const int gn = n0 + bn;
            if (gn < N) {
                const float* p = B + (size_t)gn * K + k0 + bk;
                pb[0] = *(const float4*)p;
                pb[1] = *(const float4*)(p + 4);
            } else {
                pb[0] = make_float4(0.f, 0.f, 0.f, 0.f);
                pb[1] = pb[0];
            }
        }
    };

    auto store_s = [&]() {
#pragma unroll
        for (int i = 0; i < 4; i++) {
            *(__half2*)&As[am][ak + 4 * i + 0] = __floats2half2_rn(pa[i].x, pa[i].y);
            *(__half2*)&As[am][ak + 4 * i + 2] = __floats2half2_rn(pa[i].z, pa[i].w);
        }
        if (flags & F_BKN) {
#pragma unroll
            for (int i = 0; i < 2; i++) {
                *(__half2*)&Bs[bk2][bn2 + 4 * i + 0] = __floats2half2_rn(pb[i].x, pb[i].y);
                *(__half2*)&Bs[bk2][bn2 + 4 * i + 2] = __floats2half2_rn(pb[i].z, pb[i].w);
            }
        } else {
#pragma unroll
            for (int i = 0; i < 2; i++) {
                Bs[bk + 4 * i + 0][bn] = __float2half_rn(pb[i].x);
                Bs[bk + 4 * i + 1][bn] = __float2half_rn(pb[i].y);
                Bs[bk + 4 * i + 2][bn] = __float2half_rn(pb[i].z);
                Bs[bk + 4 * i + 3][bn] = __float2half_rn(pb[i].w);
            }
        }
    };

    float acc[2][4][4];
#pragma unroll
    for (int mi = 0; mi < 2; mi++)
#pragma unroll
        for (int nj = 0; nj < 4; nj++)
#pragma unroll
            for (int r = 0; r < 4; r++) acc[mi][nj][r] = 0.f;

    const uint32_t sA = (uint32_t)__cvta_generic_to_shared(&As[0][0]);
    const uint32_t sB = (uint32_t)__cvta_generic_to_shared(&Bs[0][0]);
    const uint32_t aAddr0 = sA + (uint32_t)((wm + (lane & 15)) * 80 + ((lane >> 4) * 8) * 2);
    const uint32_t bAddr0 = sB + (uint32_t)(((lane & 15)) * 144 + (wn + (lane >> 4) * 8) * 2);

    auto compute = [&]() {
#pragma unroll
        for (int kk = 0; kk < 2; kk++) {
            uint32_t a[2][4], b[4][2];
#pragma unroll
            for (int mi = 0; mi < 2; mi++) {
                uint32_t addr = aAddr0 + (uint32_t)(mi * 16 * 80 + kk * 16 * 2);
                asm volatile("ldmatrix.sync.aligned.m8n8.x4.shared.b16 {%0,%1,%2,%3}, [%4];"
                             : "=r"(a[mi][0]), "=r"(a[mi][1]), "=r"(a[mi][2]), "=r"(a[mi][3])
                             : "r"(addr));
            }
#pragma unroll
            for (int njp = 0; njp < 2; njp++) {
                uint32_t addr = bAddr0 + (uint32_t)(kk * 16 * 144 + njp * 16 * 2);
                asm volatile("ldmatrix.sync.aligned.m8n8.x4.trans.shared.b16 {%0,%1,%2,%3}, [%4];"
                             : "=r"(b[njp * 2][0]), "=r"(b[njp * 2][1]),
                               "=r"(b[njp * 2 + 1][0]), "=r"(b[njp * 2 + 1][1])
                             : "r"(addr));
            }
#pragma unroll
            for (int mi = 0; mi < 2; mi++)
#pragma unroll
                for (int nj = 0; nj < 4; nj++) {
                    asm volatile(
                        "mma.sync.aligned.m16n8k16.row.col.f32.f16.f16.f32 "
                        "{%0,%1,%2,%3}, {%4,%5,%6,%7}, {%8,%9}, {%0,%1,%2,%3};"
                        : "+f"(acc[mi][nj][0]), "+f"(acc[mi][nj][1]),
                          "+f"(acc[mi][nj][2]), "+f"(acc[mi][nj][3])
                        : "r"(a[mi][0]), "r"(a[mi][1]), "r"(a[mi][2]), "r"(a[mi][3]),
                          "r"(b[nj][0]), "r"(b[nj][1]));
                }
        }
    };

    load_g(0);
    store_s();
    __syncthreads();
    for (int k0 = 32; k0 < K; k0 += 32) {
        load_g(k0);
        compute();
        __syncthreads();
        store_s();
        __syncthreads();
    }
    compute();

#pragma unroll
    for (int mi = 0; mi < 2; mi++)
#pragma unroll
        for (int nj = 0; nj < 4; nj++)
#pragma unroll
            for (int r = 0; r < 4; r++) {
                const int rp = r >> 1, cp = r & 1;
                const int row = m0 + wm + mi * 16 + (lane >> 2) + rp * 8;
                const int col = n0 + wn + nj * 8 + (lane & 3) * 2 + cp;
                if (row >= M || col >= N) continue;
                float v = acc[mi][nj][r];
                if (flags & F_BIAS) v += bias[col];
                const size_t idx = (size_t)row * N + col;
                if (flags & F_CHALF) ((__half*)C)[idx] = __float2half_rn(v);
                else                 ((float*)C)[idx] = v;
            }
}

// ---------------------------------------------------------------------------
// Layer-2 multi-segment GEMM: C[M,349] = sum_seg Aseg[M,256] @ Bseg[349,256]^T
// + bias.  A segments fp16, B segments f32 weights.  C written ONCE (f32).
// ---------------------------------------------------------------------------
__global__ void __launch_bounds__(256) hgemm_l2seg(
    const __half* A0, const __half* A1, const __half* A2, const __half* A3,
    const float* B0, const float* B1, const float* B2, const float* B3,
    float* __restrict__ C, const float* __restrict__ bias,
    int M, int N, int nseg)
{
    __shared__ __half As[128][40];
    __shared__ __half Bs[32][72];

    const __half* Aseg[4] = {A0, A1, A2, A3};
    const float*  Bseg[4] = {B0, B1, B2, B3};

    const int tid  = threadIdx.x;
    const int lane = tid & 31;
    const int warp = tid >> 5;
    const int wm = (warp & 3) * 32;
    const int wn = (warp >> 2) * 32;
    const int m0 = blockIdx.y * 128;
    const int n0 = blockIdx.x * 64;

    const int am = tid >> 1;
    const int ak = (tid & 1) * 16;
    const int bn = tid >> 2;
    const int bk = (tid & 3) * 8;

    uint4 pa[2];
    float4 pb[2];

    auto load_g = [&](int it) {
        const int seg = it >> 3;
        const int k0 = (it & 7) * 32;
        const int gm = m0 + am;
        if (gm < M) {
            const __half* p = Aseg[seg] + (size_t)gm * 256 + k0 + ak;
            pa[0] = *(const uint4*)p;
            pa[1] = *(const uint4*)(p + 8);
        } else {
            pa[0] = make_uint4(0, 0, 0, 0);
            pa[1] = pa[0];
        }
        const int gn = n0 + bn;
        if (gn < N) {
            const float* p = Bseg[seg] + (size_t)gn * 256 + k0 + bk;
            pb[0] = *(const float4*)p;
            pb[1] = *(const float4*)(p + 4);
        } else {
            pb[0] = make_float4(0.f, 0.f, 0.f, 0.f);
            pb[1] = pb[0];
        }
    };

    auto store_s = [&]() {
        *(uint4*)&As[am][ak]     = pa[0];
        *(uint4*)&As[am][ak + 8] = pa[1];
#pragma unroll
        for (int i = 0; i < 2; i++) {
            Bs[bk + 4 * i + 0][bn] = __float2half_rn(pb[i].x);
            Bs[bk + 4 * i + 1][bn] = __float2half_rn(pb[i].y);
            Bs[bk + 4 * i + 2][bn] = __float2half_rn(pb[i].z);
            Bs[bk + 4 * i + 3][bn] = __float2half_rn(pb[i].w);
        }
    };

    float acc[2][4][4];
#pragma unroll
    for (int mi = 0; mi < 2; mi++)
#pragma unroll
        for (int nj = 0; nj < 4; nj++)
#pragma unroll
            for (int r = 0; r < 4; r++) acc[mi][nj][r] = 0.f;

    const uint32_t sA = (uint32_t)__cvta_generic_to_shared(&As[0][0]);
    const uint32_t sB = (uint32_t)__cvta_generic_to_shared(&Bs[0][0]);
    const uint32_t aAddr0 = sA + (uint32_t)((wm + (lane & 15)) * 80 + ((lane >> 4) * 8) * 2);
    const uint32_t bAddr0 = sB + (uint32_t)(((lane & 15)) * 144 + (wn + (lane >> 4) * 8) * 2);

    auto compute = [&]() {
#pragma unroll
        for (int kk = 0; kk < 2; kk++) {
            uint32_t a[2][4], b[4][2];
#pragma unroll
            for (int mi = 0; mi < 2; mi++) {
                uint32_t addr = aAddr0 + (uint32_t)(mi * 16 * 80 + kk * 16 * 2);
                asm volatile("ldmatrix.sync.aligned.m8n8.x4.shared.b16 {%0,%1,%2,%3}, [%4];"
                             : "=r"(a[mi][0]), "=r"(a[mi][1]), "=r"(a[mi][2]), "=r"(a[mi][3])
                             : "r"(addr));
            }
#pragma unroll
            for (int njp = 0; njp < 2; njp++) {
                uint32_t addr = bAddr0 + (uint32_t)(kk * 16 * 144 + njp * 16 * 2);
                asm volatile("ldmatrix.sync.aligned.m8n8.x4.trans.shared.b16 {%0,%1,%2,%3}, [%4];"
                             : "=r"(b[njp * 2][0]), "=r"(b[njp * 2][1]),
                               "=r"(b[njp * 2 + 1][0]), "=r"(b[njp * 2 + 1][1])
                             : "r"(addr));
            }
#pragma unroll
            for (int mi = 0; mi < 2; mi++)
#pragma unroll
                for (int nj = 0; nj < 4; nj++) {
                    asm volatile(
                        "mma.sync.aligned.m16n8k16.row.col.f32.f16.f16.f32 "
                        "{%0,%1,%2,%3}, {%4,%5,%6,%7}, {%8,%9}, {%0,%1,%2,%3};"
                        : "+f"(acc[mi][nj][0]), "+f"(acc[mi][nj][1]),
                          "+f"(acc[mi][nj][2]), "+f"(acc[mi][nj][3])
                        : "r"(a[mi][0]), "r"(a[mi][1]), "r"(a[mi][2]), "r"(a[mi][3]),
                          "r"(b[nj][0]), "r"(b[nj][1]));
                }
        }
    };

    const int nit = nseg * 8;
    load_g(0);
    store_s();
    __syncthreads();
    for (int it = 1; it < nit; it++) {
        load_g(it);
        compute();
        __syncthreads();
        store_s();
        __syncthreads();
    }
    compute();

#pragma unroll
    for (int mi = 0; mi < 2; mi++)
#pragma unroll
        for (int nj = 0; nj < 4; nj++)
#pragma unroll
            for (int r = 0; r < 4; r++) {
                const int rp = r >> 1, cp = r & 1;
                const int row = m0 + wm + mi * 16 + (lane >> 2) + rp * 8;
                const int col = n0 + wn + nj * 8 + (lane & 3) * 2 + cp;
                if (row >= M || col >= N) continue;
                C[(size_t)row * N + col] = acc[mi][nj][r] + bias[col];
            }
}

// ---------------------------------------------------------------------------
// CSR build
// ---------------------------------------------------------------------------
__global__ void count_kernel(const int* __restrict__ dst_idx)
{
    const int e = blockIdx.y;
    const int i = blockIdx.x * blockDim.x + threadIdx.x;
    if (i >= E) return;
    atomicAdd(&g_cnt[c_ROFF[e] + dst_idx[(size_t)e * E + i]], 1);
}

__global__ void __launch_bounds__(256) scan1_kernel()
{
    __shared__ int s[256];
    const int tid = threadIdx.x;
    const int tbase = blockIdx.x * 2048 + tid * 8;
    int vals[8];
    int tsum = 0;
#pragma unroll
    for (int j = 0; j < 8; j++) {
        int v = (tbase + j < RTOT) ? g_cnt[tbase + j] : 0;
        vals[j] = tsum;
        tsum += v;
    }
    s[tid] = tsum;
    __syncthreads();
    for (int off = 1; off < 256; off <<= 1) {
        int t = (tid >= off) ? s[tid - off] : 0;
        __syncthreads();
        s[tid] += t;
        __syncthreads();
    }
    const int texcl = (tid > 0) ? s[tid - 1] : 0;
    if (tid == 255) g_bsum[blockIdx.x] = s[255];
#pragma unroll
    for (int j = 0; j < 8; j++)
        if (tbase + j < RTOT) g_rowptr[tbase + j] = vals[j] + texcl;
}

__global__ void __launch_bounds__(512) scan2_kernel(int nb)
{
    __shared__ int s[512];
    const int tid = threadIdx.x;
    s[tid] = (tid < nb) ? g_bsum[tid] : 0;
    __syncthreads();
    for (int off = 1; off < 512; off <<= 1) {
        int t = (tid >= off) ? s[tid - off] : 0;
        __syncthreads();
        s[tid] += t;
        __syncthreads();
    }
    g_bsum[tid] = (tid > 0) ? s[tid - 1] : 0;
}

__global__ void scan3_kernel()
{
    const int i = blockIdx.x * blockDim.x + threadIdx.x;
    if (i < RTOT) {
        int v = g_rowptr[i] + g_bsum[i >> 11];
        g_rowptr[i] = v;
        g_cursor[i] = v;
    } else if (i == RTOT) {
        g_rowptr[RTOT] = TOTE;
    }
}

__global__ void fill_kernel(const int* __restrict__ src_idx,
                            const int* __restrict__ dst_idx)
{
    const int e = blockIdx.y;
    const int i = blockIdx.x * blockDim.x + threadIdx.x;
    if (i >= E) return;
    const int d = dst_idx[(size_t)e * E + i];
    const int s = src_idx[(size_t)e * E + i];
    const int pos = atomicAdd(&g_cursor[c_ROFF[e] + d], 1);
    g_ebuf[pos] = c_OFF[c_ST[e]] + s;
}

// ---------------------------------------------------------------------------
// L1 fused: per-warp dst node. mean+max over CSR edges + root + rels, ReLU,
// single half out1 write.
// ---------------------------------------------------------------------------
__global__ void __launch_bounds__(256) l1_fused_kernel(
    __half* __restrict__ out1, const __half* __restrict__ wroot,
    int tOff, int Nn, int roff0, int roff1, int roff2, int R)
{
    __shared__ float smb[8][128];
    __shared__ float sma[8][256];

    const int warp = threadIdx.x >> 5;
    const int lane = threadIdx.x & 31;
    const int n = blockIdx.x * 8 + warp;
    if (n >= Nn) return;
    const int c4 = lane * 4;
    const int h  = lane >> 2;

    {
        const uint2 raw = *(const uint2*)(g_bases + (size_t)(tOff + n) * 128 + c4);
        const float2 lo = __half22float2(*(const __half2*)&raw.x);
        const float2 hi = __half22float2(*(const __half2*)&raw.y);
        smb[warp][c4 + 0] = lo.x; smb[warp][c4 + 1] = lo.y;
        smb[warp][c4 + 2] = hi.x; smb[warp][c4 + 3] = hi.y;
    }
    __syncwarp();

    float val[8];
    {
        const uint2 raw = *(const uint2*)(wroot + (size_t)n * 32 + h * 4);
        const float2 w01 = __half22float2(*(const __half2*)&raw.x);
        const float2 w23 = __half22float2(*(const __half2*)&raw.y);
#pragma unroll
        for (int j = 0; j < 8; j++) {
            const int dd = (lane * 8 + j) & 31;
            val[j] = w01.x * smb[warp][dd] + w01.y * smb[warp][32 + dd] +
                     w23.x * smb[warp][64 + dd] + w23.y * smb[warp][96 + dd];
        }
    }

    const int roffs[3] = {roff0, roff1, roff2};
    for (int r = 0; r < R; r++) {
        const int g = roffs[r] + n;
        const int rs = g_rowptr[g];
        const int re = g_rowptr[g + 1];
        const int ct = re - rs;
        float4 s4 = make_float4(0.f, 0.f, 0.f, 0.f);
        float4 m4 = make_float4(-INFINITY, -INFINITY, -INFINITY, -INFINITY);
        for (int k = rs; k < re; k++) {
            const uint2 raw = *(const uint2*)(g_bases + (size_t)g_ebuf[k] * 128 + c4);
            const float2 lo = __half22float2(*(const __half2*)&raw.x);
            const float2 hi = __half22float2(*(const __half2*)&raw.y);
            s4.x += lo.x; s4.y += lo.y; s4.z += hi.x; s4.w += hi.y;
            m4.x = fmaxf(m4.x, lo.x); m4.y = fmaxf(m4.y, lo.y);
            m4.z = fmaxf(m4.z, hi.x); m4.w = fmaxf(m4.w, hi.y);
        }
        const float inv = 1.f / (float)(ct > 1 ? ct : 1);
        s4.x *= inv; s4.y *= inv; s4.z *= inv; s4.w *= inv;
        if (ct == 0) m4 = make_float4(0.f, 0.f, 0.f, 0.f);
        *(float4*)&sma[warp][c4]       = s4;
        *(float4*)&sma[warp][128 + c4] = m4;
        __syncwarp();
        const uint4 raw = *(const uint4*)(g_wrel + (size_t)g * 64 + h * 8);
        const float2 w01 = __half22float2(*(const __half2*)&raw.x);
        const float2 w23 = __half22float2(*(const __half2*)&raw.y);
        const float2 w45 = __half22float2(*(const __half2*)&raw.z);
        const float2 w67 = __half22float2(*(const __half2*)&raw.w);
        const float wv[8] = {w01.x, w01.y, w23.x, w23.y, w45.x, w45.y, w67.x, w67.y};
#pragma unroll
        for (int j = 0; j < 8; j++) {
            const int dd = (lane * 8 + j) & 31;
#pragma unroll
            for (int b = 0; b < 8; b++)
                val[j] += wv[b] * sma[warp][b * 32 + dd];
        }
        __syncwarp();
    }

    union { __half2 h[4]; uint4 u; } pk;
#pragma unroll
    for (int q = 0; q < 4; q++)
        pk.h[q] = __floats2half2_rn(fmaxf(val[2 * q], 0.f), fmaxf(val[2 * q + 1], 0.f));
    *(uint4*)(out1 + (size_t)n * 256 + lane * 8) = pk.u;
}

// ---------------------------------------------------------------------------
// L2 aggregation: warp per global (rel,dst) row; mean of half out1 rows.
// ---------------------------------------------------------------------------
__global__ void __launch_bounds__(256) l2_agg_kernel()
{
    const int warp = threadIdx.x >> 5;
    const int lane = threadIdx.x & 31;
    const int g = blockIdx.x * 8 + warp;
    if (g >= RTOT) return;
    const int c8 = lane * 8;
    const int rs = g_rowptr[g];
    const int re = g_rowptr[g + 1];
    const int ct = re - rs;
    float a[8];
#pragma unroll
    for (int j = 0; j < 8; j++) a[j] = 0.f;
    for (int k = rs; k < re; k++) {
        const uint4 raw = *(const uint4*)(g_out1 + (size_t)g_ebuf[k] * 256 + c8);
        const float2 v0 = __half22float2(*(const __half2*)&raw.x);
        const float2 v1 = __half22float2(*(const __half2*)&raw.y);
        const float2 v2 = __half22float2(*(const __half2*)&raw.z);
        const float2 v3 = __half22float2(*(const __half2*)&raw.w);
        a[0] += v0.x; a[1] += v0.y; a[2] += v1.x; a[3] += v1.y;
        a[4] += v2.x; a[5] += v2.y; a[6] += v3.x; a[7] += v3.y;
    }
    const float inv = 1.f / (float)(ct > 1 ? ct : 1);
    union { __half2 h[4]; uint4 u; } pk;
#pragma unroll
    for (int q = 0; q < 4; q++)
        pk.h[q] = __floats2half2_rn(a[2 * q] * inv, a[2 * q + 1] * inv);
    *(uint4*)(g_sum2 + (size_t)g * 256 + c8) = pk.u;
}

// ---------------------------------------------------------------------------
// host
// ---------------------------------------------------------------------------
static void gemm(const float* A, const float* B, void* C, const float* bias,
                 int M, int N, int K, int flags)
{
    dim3 grid((N + 63) / 64, (M + 127) / 128);
    hgemm_kernel<<<grid, 256>>>(A, B, C, bias, M, N, K, flags);
}

extern "C" void kernel_launch(void* const* d_in, const int* in_sizes, int n_in,
                              void* d_out, int out_size)
{
    const float* x_paper    = (const float*)d_in[0];
    const float* emb_author = (const float*)d_in[1];
    const float* emb_fos    = (const float*)d_in[2];
    const float* emb_inst   = (const float*)d_in[3];
    const float* bases_w1   = (const float*)d_in[4];
    const float* rel_w1     = (const float*)d_in[5];
    const float* rel_b1     = (const float*)d_in[6];
    const float* root_w1    = (const float*)d_in[7];
    const float* root_b1    = (const float*)d_in[8];
    const float* rel_w2     = (const float*)d_in[9];
    const float* root_w2    = (const float*)d_in[10];
    const float* root_b2    = (const float*)d_in[11];
    const int*   src_idx    = (const int*)d_in[12];
    const int*   dst_idx    = (const int*)d_in[13];
    float* out = (float*)d_out;

    static const int NUMSh[4] = {200000, 30000, 5000, 150000};
    static const int OFFh[4]  = {0, 200000, 230000, 235000};
    static const int DT[7] = {2, 0, 3, 0, 3, 1, 3};
    static const int ROFFh[7] = {0, 5000, 205000, 355000, 555000, 705000, 735000};

    __half *bases_p, *out1_p, *wroot_p, *wrel_p, *sum2_p;
    int* cnt_p;
    cudaGetSymbolAddress((void**)&bases_p, g_bases);
    cudaGetSymbolAddress((void**)&out1_p,  g_out1);
    cudaGetSymbolAddress((void**)&wroot_p, g_wroot);
    cudaGetSymbolAddress((void**)&wrel_p,  g_wrel);
    cudaGetSymbolAddress((void**)&sum2_p,  g_sum2);
    cudaGetSymbolAddress((void**)&cnt_p,   g_cnt);

    const float* xs[4] = {emb_author, emb_fos, emb_inst, x_paper};

    // ---- CSR build ----
    cudaMemsetAsync(cnt_p, 0, (size_t)RTOT * sizeof(int));
    {
        dim3 grid((E + 255) / 256, 7);
        count_kernel<<<grid, 256>>>(dst_idx);
    }
    scan1_kernel<<<(RTOT + 2047) / 2048, 256>>>();
    scan2_kernel<<<1, 512>>>((RTOT + 2047) / 2048);
    scan3_kernel<<<(RTOT + 1 + 255) / 256, 256>>>();
    {
        dim3 grid((E + 255) / 256, 7);
        fill_kernel<<<grid, 256>>>(src_idx, dst_idx);
    }

    // ---- layer-1 GEMMs (outputs fp16) ----
    for (int t = 0; t < 4; t++)
        gemm(xs[t], bases_w1, bases_p + (size_t)OFFh[t] * 128,
             nullptr, NUMSh[t], 128, 128, F_BKN | F_CHALF);
    for (int t = 0; t < 4; t++)
        gemm(xs[t], root_w1 + (size_t)t * 32 * 128, wroot_p + (size_t)OFFh[t] * 32,
             root_b1 + t * 32, NUMSh[t], 32, 128, F_BIAS | F_CHALF);
    for (int e = 0; e < 7; e++)
        gemm(xs[DT[e]], rel_w1 + (size_t)e * 64 * 128, wrel_p + (size_t)ROFFh[e] * 64,
             rel_b1 + e * 64, NUMSh[DT[e]], 64, 128, F_BIAS | F_CHALF);

    // ---- layer-1 fused aggregate+combine ----
    for (int t = 0; t < 4; t++) {
        int ro[3] = {0, 0, 0};
        int R = 0;
        for (int e = 0; e < 7; e++)
            if (DT[e] == t) ro[R++] = ROFFh[e];
        l1_fused_kernel<<<(NUMSh[t] + 7) / 8, 256>>>(
            out1_p + (size_t)OFFh[t] * 256, wroot_p + (size_t)OFFh[t] * 32,
            OFFh[t], NUMSh[t], ro[0], ro[1], ro[2], R);
    }

    // ---- layer-2 aggregation ----
    l2_agg_kernel<<<(RTOT + 7) / 8, 256>>>();

    // ---- layer-2: one multi-segment GEMM per destination type ----
    for (int t = 0; t < 4; t++) {
        const __half* A[4] = {out1_p + (size_t)OFFh[t] * 256, nullptr, nullptr, nullptr};
        const float*  B[4] = {root_w2 + (size_t)t * 349 * 256, nullptr, nullptr, nullptr};
        int nseg = 1;
        for (int e = 0; e < 7; e++) {
            if (DT[e] != t) continue;
            A[nseg] = sum2_p + (size_t)ROFFh[e] * 256;
            B[nseg] = rel_w2 + (size_t)e * 349 * 256;
            nseg++;
        }
        for (int s2 = nseg; s2 < 4; s2++) { A[s2] = A[0]; B[s2] = B[0]; }
        dim3 grid((349 + 63) / 64, (NUMSh[t] + 127) / 128);
        hgemm_l2seg<<<grid, 256>>>(A[0], A[1], A[2], A[3],
                                   B[0], B[1], B[2], B[3],
                                   out + (size_t)OFFh[t] * 349, root_b2 + t * 349,
                                   NUMSh[t], 349, nseg);
    }
}